// round 9
// baseline (speedup 1.0000x reference)
#include <cuda_runtime.h>
#include <cuda_bf16.h>

#define NNODES 50000
#define NEDGE  1600000

constexpr size_t AL(size_t x) { return (x + 255) & ~(size_t)255; }
constexpr size_t O_DEG  = 0;
constexpr size_t O_DIS  = AL(O_DEG  + (size_t)NNODES*4);
constexpr size_t O_NORM = AL(O_DIS  + (size_t)NNODES*4);
constexpr size_t O_CNT  = AL(O_NORM + (size_t)NEDGE*4);
constexpr size_t O_CPTR = AL(O_CNT  + (size_t)NNODES*4);
constexpr size_t O_CUR  = AL(O_CPTR + (size_t)(NNODES+1)*4);
constexpr size_t O_EROW = AL(O_CUR  + (size_t)NNODES*4);
constexpr size_t O_ENRM = AL(O_EROW + (size_t)NEDGE*4);
constexpr size_t O_TX1  = AL(O_ENRM + (size_t)NEDGE*4);
constexpr size_t O_TX2  = AL(O_TX1  + (size_t)NNODES*512*4);
constexpr size_t O_H1   = AL(O_TX2  + (size_t)NNODES*512*4);
constexpr size_t O_Z6   = AL(O_H1   + (size_t)NNODES*1200*4);
constexpr size_t O_Q    = AL(O_Z6   + (size_t)NNODES*600*4);
constexpr size_t O_WP1  = AL(O_Q    + (size_t)NNODES*100*4);
constexpr size_t O_WP1B = AL(O_WP1  + (size_t)512*1200*4);
constexpr size_t O_WP2  = AL(O_WP1B + (size_t)512*800*4);
constexpr size_t O_SUM  = AL(O_WP2  + (size_t)1200*600*4);
constexpr size_t O_SSQ  = AL(O_SUM  + (size_t)1200*4);
constexpr size_t O_S    = AL(O_SSQ  + (size_t)1200*4);
constexpr size_t O_T    = AL(O_S    + (size_t)1200*4);
constexpr size_t SCRATCH_BYTES = AL(O_T + (size_t)1200*4);

__device__ __align__(256) unsigned char g_scratch[SCRATCH_BYTES];

// ------------------------- f32x2 helpers -------------------------
__device__ __forceinline__ unsigned long long ffma2(unsigned long long a,
                                                    unsigned long long b,
                                                    unsigned long long c) {
    unsigned long long d;
    asm("fma.rn.f32x2 %0, %1, %2, %3;" : "=l"(d) : "l"(a), "l"(b), "l"(c));
    return d;
}
__device__ __forceinline__ unsigned long long pack2(float lo, float hi) {
    unsigned long long d;
    asm("mov.b64 %0, {%1, %2};" : "=l"(d) : "f"(lo), "f"(hi));
    return d;
}
__device__ __forceinline__ float2 unpack2(unsigned long long u) {
    float2 f;
    asm("mov.b64 {%0, %1}, %2;" : "=f"(f.x), "=f"(f.y) : "l"(u));
    return f;
}

// ------------------------- graph prep -------------------------
__global__ void deg_kernel(const int* __restrict__ row, const float* __restrict__ w,
                           float* __restrict__ deg, int E) {
    for (int e = blockIdx.x * blockDim.x + threadIdx.x; e < E; e += gridDim.x * blockDim.x)
        atomicAdd(&deg[row[e]], w[e]);
}

__global__ void dis_kernel(const float* __restrict__ deg, float* __restrict__ dis, int n) {
    int i = blockIdx.x * blockDim.x + threadIdx.x;
    if (i < n) { float d = deg[i]; dis[i] = (d > 0.f) ? rsqrtf(d) : 0.f; }
}

__global__ void norm_cnt_kernel(const int* __restrict__ row, const int* __restrict__ col,
                                const float* __restrict__ w, const float* __restrict__ dis,
                                float* __restrict__ nrm, int* __restrict__ cnt, int E) {
    for (int e = blockIdx.x * blockDim.x + threadIdx.x; e < E; e += gridDim.x * blockDim.x) {
        int r = row[e], c = col[e];
        nrm[e] = -dis[r] * w[e] * dis[c];
        atomicAdd(&cnt[c], 1);
    }
}

__global__ void scan_kernel(const int* __restrict__ cnt, int n, int* __restrict__ colptr) {
    __shared__ int part[1024];
    int tid = threadIdx.x;
    int per = (n + 1023) / 1024;
    int s0 = tid * per, s1 = min(s0 + per, n);
    int s = 0;
    for (int i = s0; i < s1; i++) s += cnt[i];
    part[tid] = s;
    __syncthreads();
    for (int off = 1; off < 1024; off <<= 1) {
        int v = (tid >= off) ? part[tid - off] : 0;
        __syncthreads();
        part[tid] += v;
        __syncthreads();
    }
    int prefix = (tid == 0) ? 0 : part[tid - 1];
    for (int i = s0; i < s1; i++) { colptr[i] = prefix; prefix += cnt[i]; }
    if (tid == 0) colptr[n] = part[1023];
}

__global__ void scatter_kernel(const int* __restrict__ row, const int* __restrict__ col,
                               const float* __restrict__ nrm, int* __restrict__ cursor,
                               int* __restrict__ erow, float* __restrict__ enorm, int E) {
    for (int e = blockIdx.x * blockDim.x + threadIdx.x; e < E; e += gridDim.x * blockDim.x) {
        int c = col[e];
        int p = atomicAdd(&cursor[c], 1);
        erow[p] = row[e];
        enorm[p] = nrm[e];
    }
}

// ------------------------- weight packing -------------------------
__global__ void pack_cols(float* __restrict__ dst, int dstLd, int dstOff,
                          const float* __restrict__ src, int srcCols, int rows) {
    int total = rows * srcCols;
    for (int i = blockIdx.x * blockDim.x + threadIdx.x; i < total; i += gridDim.x * blockDim.x) {
        int r = i / srcCols, c = i - r * srcCols;
        dst[(size_t)r * dstLd + dstOff + c] = src[i];
    }
}

// ------------------------- SGEMM 128x128x8, f32x2 -------------------------
// C[M,N] (+)= A[M,K] @ B[K,N]; row-major; K%8==0, N%4==0.
__global__ __launch_bounds__(256, 2)
void sgemm_kernel(int M, int N, int K,
                  const float* __restrict__ A, int lda,
                  const float* __restrict__ B, int ldb,
                  float* __restrict__ C, int ldc, int accum) {
    __shared__ __align__(16) float As[8][128];
    __shared__ __align__(16) float Bs[8][128];
    const int tid = threadIdx.x;
    const int bm = blockIdx.y * 128, bn = blockIdx.x * 128;
    const int aRow = tid >> 1, aK4 = (tid & 1) << 2;
    const int bRow = tid >> 5, bC4 = (tid & 31) << 2;
    const int ty = tid >> 4, tx = tid & 15;

    unsigned long long acc[8][4];
#pragma unroll
    for (int i = 0; i < 8; i++)
#pragma unroll
        for (int j = 0; j < 4; j++) acc[i][j] = 0ULL;

    const bool aValid = (bm + aRow) < M;
    const bool bValid = (bn + bC4) < N;
    const float* Ap = A + (size_t)(bm + aRow) * lda + aK4;
    const float* Bp = B + (size_t)bRow * ldb + bn + bC4;

    float4 av = make_float4(0,0,0,0), bv = make_float4(0,0,0,0);
    if (aValid) av = *reinterpret_cast<const float4*>(Ap);
    if (bValid) bv = *reinterpret_cast<const float4*>(Bp);

    for (int k0 = 0; k0 < K; k0 += 8) {
        As[aK4 + 0][aRow] = av.x; As[aK4 + 1][aRow] = av.y;
        As[aK4 + 2][aRow] = av.z; As[aK4 + 3][aRow] = av.w;
        *reinterpret_cast<float4*>(&Bs[bRow][bC4]) = bv;
        __syncthreads();
        int kn = k0 + 8;
        if (kn < K) {
            if (aValid) av = *reinterpret_cast<const float4*>(Ap + kn);
            if (bValid) bv = *reinterpret_cast<const float4*>(Bp + (size_t)kn * ldb);
        }
#pragma unroll
        for (int kk = 0; kk < 8; kk++) {
            float4 a0 = *reinterpret_cast<const float4*>(&As[kk][ty * 4]);
            float4 a1 = *reinterpret_cast<const float4*>(&As[kk][ty * 4 + 64]);
            ulonglong2 b0 = *reinterpret_cast<const ulonglong2*>(&Bs[kk][tx * 4]);
            ulonglong2 b1 = *reinterpret_cast<const ulonglong2*>(&Bs[kk][tx * 4 + 64]);
            unsigned long long bp[4] = { b0.x, b0.y, b1.x, b1.y };
            float a[8] = { a0.x, a0.y, a0.z, a0.w, a1.x, a1.y, a1.z, a1.w };
#pragma unroll
            for (int i = 0; i < 8; i++) {
                unsigned long long ai = pack2(a[i], a[i]);
#pragma unroll
                for (int j = 0; j < 4; j++)
                    acc[i][j] = ffma2(ai, bp[j], acc[i][j]);
            }
        }
        __syncthreads();
    }

#pragma unroll
    for (int rh = 0; rh < 2; rh++)
#pragma unroll
        for (int i = 0; i < 4; i++) {
            int rrow = bm + rh * 64 + ty * 4 + i;
            if (rrow >= M) continue;
            int ai = rh * 4 + i;
#pragma unroll
            for (int ch = 0; ch < 2; ch++) {
                int ccol = bn + ch * 64 + tx * 4;
                if (ccol >= N) continue;
                float2 p0 = unpack2(acc[ai][ch * 2 + 0]);
                float2 p1 = unpack2(acc[ai][ch * 2 + 1]);
                float4 r = make_float4(p0.x, p0.y, p1.x, p1.y);
                float* cp = C + (size_t)rrow * ldc + ccol;
                if (accum) {
                    float4 o = *reinterpret_cast<const float4*>(cp);
                    r.x += o.x; r.y += o.y; r.z += o.z; r.w += o.w;
                }
                *reinterpret_cast<float4*>(cp) = r;
            }
        }
}

static void run_sgemm(int M, int N, int K, const float* A, int lda,
                      const float* B, int ldb, float* C, int ldc, int accum) {
    dim3 grid((N + 127) / 128, (M + 127) / 128);
    sgemm_kernel<<<grid, 256>>>(M, N, K, A, lda, B, ldb, C, ldc, accum);
}

// ------------------------- CSR prop -------------------------
// dst[c] = (accum?dst[c]:0) + alpha*sum_e norm_e*src[row_e] + beta*other[c]
__global__ void prop_kernel(const float4* __restrict__ src, int srcLd4,
                            float4* __restrict__ dst, int dstLd4, int D4,
                            float alpha, const float4* __restrict__ other, int otherLd4,
                            float beta, int accum,
                            const int* __restrict__ colptr, const int* __restrict__ erow,
                            const float* __restrict__ enorm) {
    int c = blockIdx.x, tid = threadIdx.x;
    __shared__ int sR[256];
    __shared__ float sW[256];
    int e0 = colptr[c], e1 = colptr[c + 1];
    float4 acc = make_float4(0,0,0,0);
    for (int base = e0; base < e1; base += 256) {
        int cnt = min(256, e1 - base);
        for (int i = tid; i < cnt; i += blockDim.x) {
            sR[i] = erow[base + i];
            sW[i] = enorm[base + i];
        }
        __syncthreads();
        if (tid < D4) {
            for (int i = 0; i < cnt; i++) {
                float w = sW[i];
                float4 v = src[(size_t)sR[i] * srcLd4 + tid];
                acc.x += w * v.x; acc.y += w * v.y;
                acc.z += w * v.z; acc.w += w * v.w;
            }
        }
        __syncthreads();
    }
    if (tid < D4) {
        float4 r = make_float4(alpha*acc.x, alpha*acc.y, alpha*acc.z, alpha*acc.w);
        if (other) {
            float4 ov = other[(size_t)c * otherLd4 + tid];
            r.x += beta*ov.x; r.y += beta*ov.y; r.z += beta*ov.z; r.w += beta*ov.w;
        }
        size_t o = (size_t)c * dstLd4 + tid;
        if (accum) {
            float4 d = dst[o];
            r.x += d.x; r.y += d.y; r.z += d.z; r.w += d.w;
        }
        dst[o] = r;
    }
}

// ------------------------- batchnorm -------------------------
__global__ void bn_stats(const float* __restrict__ H, int ld, int C, int rows,
                         int rpb, float* __restrict__ gsum, float* __restrict__ gsq) {
    int c = blockIdx.x * blockDim.x + threadIdx.x;
    if (c >= C) return;
    int r0 = blockIdx.y * rpb, r1 = min(r0 + rpb, rows);
    float s = 0.f, q = 0.f;
    for (int r = r0; r < r1; r++) {
        float v = H[(size_t)r * ld + c];
        s += v; q += v * v;
    }
    atomicAdd(&gsum[c], s);
    atomicAdd(&gsq[c], q);
}

__global__ void bn_finalize(const float* __restrict__ gsum, const float* __restrict__ gsq,
                            const float* __restrict__ g, const float* __restrict__ beta,
                            float* __restrict__ s, float* __restrict__ t, int C, float invN) {
    int c = blockIdx.x * blockDim.x + threadIdx.x;
    if (c >= C) return;
    float mu = gsum[c] * invN;
    float var = gsq[c] * invN - mu * mu;
    float rs = rsqrtf(var + 1e-5f) * g[c];
    s[c] = rs;
    t[c] = beta[c] - mu * rs;
}

__global__ void bn_apply_relu(float4* __restrict__ H, const float* __restrict__ s,
                              const float* __restrict__ t, size_t total4, int C4) {
    for (size_t i = blockIdx.x * (size_t)blockDim.x + threadIdx.x; i < total4;
         i += (size_t)gridDim.x * blockDim.x) {
        int c = (int)(i % C4) * 4;
        float4 v = H[i];
        v.x = fmaxf(fmaf(v.x, s[c+0], t[c+0]), 0.f);
        v.y = fmaxf(fmaf(v.y, s[c+1], t[c+1]), 0.f);
        v.z = fmaxf(fmaf(v.z, s[c+2], t[c+2]), 0.f);
        v.w = fmaxf(fmaf(v.w, s[c+3], t[c+3]), 0.f);
        H[i] = v;
    }
}

// ---------------- final: BN2 + linear(300->10) + logsoftmax ----------------
__global__ void final_kernel(const float* __restrict__ Z, int ld,
                             const float* __restrict__ s, const float* __restrict__ t,
                             const float* __restrict__ Wl, const float* __restrict__ bl,
                             float* __restrict__ out, int rows) {
    __shared__ float sW[3000], ss[300], st[300], sb[16];
    int tid = threadIdx.x;
    for (int i = tid; i < 3000; i += 256) sW[i] = Wl[i];
    for (int i = tid; i < 300; i += 256) { ss[i] = s[i]; st[i] = t[i]; }
    if (tid < 10) sb[tid] = bl[tid];
    __syncthreads();
    int warp = tid >> 5, lane = tid & 31;
    int row = blockIdx.x * 8 + warp;
    if (row >= rows) return;
    float acc[10];
#pragma unroll
    for (int j = 0; j < 10; j++) acc[j] = 0.f;
    const float* zr = Z + (size_t)row * ld;
    for (int k = lane; k < 300; k += 32) {
        float h = fmaf(zr[k], ss[k], st[k]);
#pragma unroll
        for (int j = 0; j < 10; j++) acc[j] += h * sW[k * 10 + j];
    }
#pragma unroll
    for (int j = 0; j < 10; j++) {
#pragma unroll
        for (int o = 16; o > 0; o >>= 1) acc[j] += __shfl_xor_sync(0xffffffffu, acc[j], o);
        acc[j] += sb[j];
    }
    float m = acc[0];
#pragma unroll
    for (int j = 1; j < 10; j++) m = fmaxf(m, acc[j]);
    float sum = 0.f;
#pragma unroll
    for (int j = 0; j < 10; j++) sum += expf(acc[j] - m);
    float lse = m + logf(sum);
    if (lane < 10) out[(size_t)row * 10 + lane] = acc[lane] - lse;
}

// ------------------------- launch -------------------------
extern "C" void kernel_launch(void* const* d_in, const int* in_sizes, int n_in,
                              void* d_out, int out_size) {
    const float* x   = (const float*)d_in[0];
    const int*   eix = (const int*)  d_in[1];
    const float* ew  = (const float*)d_in[2];
    const float* W1a = (const float*)d_in[3];
    const float* W1b = (const float*)d_in[5];
    const float* W1c = (const float*)d_in[7];
    const float* g1  = (const float*)d_in[9];
    const float* be1 = (const float*)d_in[10];
    const float* W2a = (const float*)d_in[11];
    const float* W2b = (const float*)d_in[13];
    const float* W2c = (const float*)d_in[15];
    const float* g2  = (const float*)d_in[17];
    const float* be2 = (const float*)d_in[18];
    const float* Wl  = (const float*)d_in[19];
    const float* bl  = (const float*)d_in[20];
    float* out = (float*)d_out;

    unsigned char* base = nullptr;
    cudaGetSymbolAddress((void**)&base, g_scratch);

    float* deg  = (float*)(base + O_DEG);
    float* dis  = (float*)(base + O_DIS);
    float* nrm  = (float*)(base + O_NORM);
    int*   cnt  = (int*)  (base + O_CNT);
    int*   cptr = (int*)  (base + O_CPTR);
    int*   cur  = (int*)  (base + O_CUR);
    int*   erow = (int*)  (base + O_EROW);
    float* enrm = (float*)(base + O_ENRM);
    float* Tx1  = (float*)(base + O_TX1);
    float* Tx2  = (float*)(base + O_TX2);
    float* H1   = (float*)(base + O_H1);
    float* Z6   = (float*)(base + O_Z6);
    float* Q    = (float*)(base + O_Q);
    float* Wp1  = (float*)(base + O_WP1);
    float* Wp1b = (float*)(base + O_WP1B);
    float* Wp2  = (float*)(base + O_WP2);
    float* gsum = (float*)(base + O_SUM);
    float* gsq  = (float*)(base + O_SSQ);
    float* bnS  = (float*)(base + O_S);
    float* bnT  = (float*)(base + O_T);

    const int* row = eix;
    const int* col = eix + NEDGE;

    // graph prep: degrees, norm, CSR-by-destination
    cudaMemsetAsync(deg, 0, (size_t)NNODES * 4);
    cudaMemsetAsync(cnt, 0, (size_t)NNODES * 4);
    deg_kernel<<<4096, 256>>>(row, ew, deg, NEDGE);
    dis_kernel<<<(NNODES + 255) / 256, 256>>>(deg, dis, NNODES);
    norm_cnt_kernel<<<4096, 256>>>(row, col, ew, dis, nrm, cnt, NEDGE);
    scan_kernel<<<1, 1024>>>(cnt, NNODES, cptr);
    cudaMemcpyAsync(cur, cptr, (size_t)NNODES * 4, cudaMemcpyDeviceToDevice);
    scatter_kernel<<<4096, 256>>>(row, col, nrm, cur, erow, enrm, NEDGE);

    // weight packing (conv biases cancel under BN — dropped)
    pack_cols<<<256, 256>>>(Wp1, 1200, 0,   W1a,          400, 512);
    pack_cols<<<256, 256>>>(Wp1, 1200, 400, W1b,          400, 512);
    pack_cols<<<256, 256>>>(Wp1, 1200, 800, W1c,          400, 512);
    pack_cols<<<256, 256>>>(Wp1b, 800, 0,   W1b + 204800, 400, 512);
    pack_cols<<<256, 256>>>(Wp1b, 800, 400, W1c + 204800, 400, 512);
    pack_cols<<<256, 256>>>(Wp2, 600, 0,    W2a,          100, 1200);
    pack_cols<<<256, 256>>>(Wp2, 600, 100,  W2b,          100, 1200);
    pack_cols<<<256, 256>>>(Wp2, 600, 200,  W2c,          100, 1200);
    pack_cols<<<256, 256>>>(Wp2, 600, 300,  W2b + 120000, 100, 1200);
    pack_cols<<<256, 256>>>(Wp2, 600, 400,  W2c + 120000, 100, 1200);
    pack_cols<<<256, 256>>>(Wp2, 600, 500,  W2c + 240000, 100, 1200);

    // layer 1
    run_sgemm(NNODES, 1200, 512, x, 512, Wp1, 1200, H1, 1200, 0);
    prop_kernel<<<NNODES, 128>>>((const float4*)x, 128, (float4*)Tx1, 128, 128,
                                 1.f, nullptr, 0, 0.f, 0, cptr, erow, enrm);
    run_sgemm(NNODES, 800, 512, Tx1, 512, Wp1b, 800, H1 + 400, 1200, 1);
    prop_kernel<<<NNODES, 128>>>((const float4*)Tx1, 128, (float4*)Tx2, 128, 128,
                                 2.f, (const float4*)x, 128, -1.f, 0, cptr, erow, enrm);
    run_sgemm(NNODES, 400, 512, Tx2, 512, W1c + 409600, 400, H1 + 800, 1200, 1);

    // BN1 + ReLU
    cudaMemsetAsync(gsum, 0, 1200 * 4);
    cudaMemsetAsync(gsq, 0, 1200 * 4);
    {
        dim3 g((1200 + 255) / 256, 20);
        bn_stats<<<g, 256>>>(H1, 1200, 1200, NNODES, 2500, gsum, gsq);
    }
    bn_finalize<<<(1200 + 255) / 256, 256>>>(gsum, gsq, g1, be1, bnS, bnT, 1200, 1.f / NNODES);
    bn_apply_relu<<<4096, 256>>>((float4*)H1, bnS, bnT, (size_t)NNODES * 300, 300);

    // layer 2: GEMM-first (prop commutes with W)
    run_sgemm(NNODES, 600, 1200, H1, 1200, Wp2, 600, Z6, 600, 0);
    // Z6[:,100:300] += prop(Z6[:,300:500])
    prop_kernel<<<NNODES, 64>>>((const float4*)(Z6 + 300), 150, (float4*)(Z6 + 100), 150, 50,
                                1.f, nullptr, 0, 0.f, 1, cptr, erow, enrm);
    // Q = prop(Z6[:,500:600])
    prop_kernel<<<NNODES, 32>>>((const float4*)(Z6 + 500), 150, (float4*)Q, 25, 25,
                                1.f, nullptr, 0, 0.f, 0, cptr, erow, enrm);
    // Z6[:,200:300] += 2*prop(Q) - Z6[:,500:600]
    prop_kernel<<<NNODES, 32>>>((const float4*)Q, 25, (float4*)(Z6 + 200), 150, 25,
                                2.f, (const float4*)(Z6 + 500), 150, -1.f, 1, cptr, erow, enrm);

    // BN2 stats
    cudaMemsetAsync(gsum, 0, 300 * 4);
    cudaMemsetAsync(gsq, 0, 300 * 4);
    {
        dim3 g((300 + 255) / 256, 20);
        bn_stats<<<g, 256>>>(Z6, 600, 300, NNODES, 2500, gsum, gsq);
    }
    bn_finalize<<<(300 + 255) / 256, 256>>>(gsum, gsq, g2, be2, bnS, bnT, 300, 1.f / NNODES);

    // fused BN2 + linear + log_softmax
    final_kernel<<<(NNODES + 7) / 8, 256>>>(Z6, 600, bnS, bnT, Wl, bl, out, NNODES);
}

// round 10
// speedup vs baseline: 1.3732x; 1.3732x over previous
#include <cuda_runtime.h>
#include <cuda_bf16.h>

#define NNODES 50000
#define NEDGE  1600000

using bf16 = __nv_bfloat16;
using bf162 = __nv_bfloat162;

constexpr size_t AL(size_t x) { return (x + 255) & ~(size_t)255; }
constexpr size_t O_DEG  = 0;
constexpr size_t O_DIS  = AL(O_DEG  + (size_t)NNODES*4);
constexpr size_t O_NORM = AL(O_DIS  + (size_t)NNODES*4);
constexpr size_t O_CNT  = AL(O_NORM + (size_t)NEDGE*4);
constexpr size_t O_CPTR = AL(O_CNT  + (size_t)NNODES*4);
constexpr size_t O_CUR  = AL(O_CPTR + (size_t)(NNODES+1)*4);
constexpr size_t O_EROW = AL(O_CUR  + (size_t)NNODES*4);
constexpr size_t O_ENRM = AL(O_EROW + (size_t)NEDGE*4);
constexpr size_t O_TX1  = AL(O_ENRM + (size_t)NEDGE*4);
constexpr size_t O_TX2  = AL(O_TX1  + (size_t)NNODES*512*4);
constexpr size_t O_H1   = AL(O_TX2  + (size_t)NNODES*512*4);
constexpr size_t O_Z6   = AL(O_H1   + (size_t)NNODES*1200*4);
constexpr size_t O_Q    = AL(O_Z6   + (size_t)NNODES*600*4);
constexpr size_t O_WP1  = AL(O_Q    + (size_t)NNODES*100*4);
constexpr size_t O_WP1B = AL(O_WP1  + (size_t)512*1200*4);
constexpr size_t O_WP2  = AL(O_WP1B + (size_t)512*800*4);
constexpr size_t O_SUM  = AL(O_WP2  + (size_t)1200*600*4);
constexpr size_t O_SSQ  = AL(O_SUM  + (size_t)1200*4);
constexpr size_t O_S    = AL(O_SSQ  + (size_t)1200*4);
constexpr size_t O_T    = AL(O_S    + (size_t)1200*4);
// bf16 splits
constexpr size_t O_XH  = AL(O_T   + (size_t)1200*4);
constexpr size_t O_XL  = AL(O_XH  + (size_t)NNODES*512*2);
constexpr size_t O_T1H = AL(O_XL  + (size_t)NNODES*512*2);
constexpr size_t O_T1L = AL(O_T1H + (size_t)NNODES*512*2);
constexpr size_t O_T2H = AL(O_T1L + (size_t)NNODES*512*2);
constexpr size_t O_T2L = AL(O_T2H + (size_t)NNODES*512*2);
constexpr size_t O_H1H = AL(O_T2L + (size_t)NNODES*512*2);
constexpr size_t O_H1L = AL(O_H1H + (size_t)NNODES*1200*2);
constexpr size_t O_W1H = AL(O_H1L + (size_t)NNODES*1200*2);
constexpr size_t O_W1L = AL(O_W1H + (size_t)512*1200*2);
constexpr size_t O_W1BH= AL(O_W1L + (size_t)512*1200*2);
constexpr size_t O_W1BL= AL(O_W1BH+ (size_t)512*800*2);
constexpr size_t O_W1CH= AL(O_W1BL+ (size_t)512*800*2);
constexpr size_t O_W1CL= AL(O_W1CH+ (size_t)512*400*2);
constexpr size_t O_W2H = AL(O_W1CL+ (size_t)512*400*2);
constexpr size_t O_W2L = AL(O_W2H + (size_t)1200*600*2);
constexpr size_t SCRATCH_BYTES = AL(O_W2L + (size_t)1200*600*2);

__device__ __align__(256) unsigned char g_scratch[SCRATCH_BYTES];

// ------------------------- graph prep -------------------------
__global__ void deg_kernel(const int* __restrict__ row, const float* __restrict__ w,
                           float* __restrict__ deg, int E) {
    for (int e = blockIdx.x * blockDim.x + threadIdx.x; e < E; e += gridDim.x * blockDim.x)
        atomicAdd(&deg[row[e]], w[e]);
}

__global__ void dis_kernel(const float* __restrict__ deg, float* __restrict__ dis, int n) {
    int i = blockIdx.x * blockDim.x + threadIdx.x;
    if (i < n) { float d = deg[i]; dis[i] = (d > 0.f) ? rsqrtf(d) : 0.f; }
}

__global__ void norm_cnt_kernel(const int* __restrict__ row, const int* __restrict__ col,
                                const float* __restrict__ w, const float* __restrict__ dis,
                                float* __restrict__ nrm, int* __restrict__ cnt, int E) {
    for (int e = blockIdx.x * blockDim.x + threadIdx.x; e < E; e += gridDim.x * blockDim.x) {
        int r = row[e], c = col[e];
        nrm[e] = -dis[r] * w[e] * dis[c];
        atomicAdd(&cnt[c], 1);
    }
}

__global__ void scan_kernel(const int* __restrict__ cnt, int n, int* __restrict__ colptr) {
    __shared__ int part[1024];
    int tid = threadIdx.x;
    int per = (n + 1023) / 1024;
    int s0 = tid * per, s1 = min(s0 + per, n);
    int s = 0;
    for (int i = s0; i < s1; i++) s += cnt[i];
    part[tid] = s;
    __syncthreads();
    for (int off = 1; off < 1024; off <<= 1) {
        int v = (tid >= off) ? part[tid - off] : 0;
        __syncthreads();
        part[tid] += v;
        __syncthreads();
    }
    int prefix = (tid == 0) ? 0 : part[tid - 1];
    for (int i = s0; i < s1; i++) { colptr[i] = prefix; prefix += cnt[i]; }
    if (tid == 0) colptr[n] = part[1023];
}

__global__ void scatter_kernel(const int* __restrict__ row, const int* __restrict__ col,
                               const float* __restrict__ nrm, int* __restrict__ cursor,
                               int* __restrict__ erow, float* __restrict__ enorm, int E) {
    for (int e = blockIdx.x * blockDim.x + threadIdx.x; e < E; e += gridDim.x * blockDim.x) {
        int c = col[e];
        int p = atomicAdd(&cursor[c], 1);
        erow[p] = row[e];
        enorm[p] = nrm[e];
    }
}

// ------------------------- weight packing + bf16 split -------------------------
__global__ void pack_cols(float* __restrict__ dst, int dstLd, int dstOff,
                          const float* __restrict__ src, int srcCols, int rows) {
    int total = rows * srcCols;
    for (int i = blockIdx.x * blockDim.x + threadIdx.x; i < total; i += gridDim.x * blockDim.x) {
        int r = i / srcCols, c = i - r * srcCols;
        dst[(size_t)r * dstLd + dstOff + c] = src[i];
    }
}

__global__ void split_kernel(const float2* __restrict__ src, bf162* __restrict__ hi,
                             bf162* __restrict__ lo, size_t n2) {
    for (size_t i = blockIdx.x * (size_t)blockDim.x + threadIdx.x; i < n2;
         i += (size_t)gridDim.x * blockDim.x) {
        float2 v = src[i];
        bf16 ax = __float2bfloat16(v.x), ay = __float2bfloat16(v.y);
        bf162 h; h.x = ax; h.y = ay;
        bf162 l;
        l.x = __float2bfloat16(v.x - __bfloat162float(ax));
        l.y = __float2bfloat16(v.y - __bfloat162float(ay));
        hi[i] = h; lo[i] = l;
    }
}

// ------------------------- bf16 split-GEMM (tensor pipe) -------------------------
// C[M,N] (+)= Ah*Bh + Ah*Bl + Al*Bh  (fp32 accum), row-major. K%16==0, N%16==0.
__device__ __forceinline__ unsigned s2u(const void* p) {
    return (unsigned)__cvta_generic_to_shared(p);
}

#define APAD 24   // sA row stride in bf16 (48B: 8-row LDSM offsets all distinct mod 128B)
#define BPAD 136  // sB row stride in bf16 (272B)

__global__ __launch_bounds__(256, 2)
void bgemm_kernel(int M, int N, int K,
                  const bf16* __restrict__ Ah, const bf16* __restrict__ Al, int lda,
                  const bf16* __restrict__ Bh, const bf16* __restrict__ Bl, int ldb,
                  float* __restrict__ C, int ldc, int accum) {
    __shared__ __align__(16) bf16 sA[128 * APAD];
    __shared__ __align__(16) bf16 sB[16 * BPAD];

    const int tid = threadIdx.x, lane = tid & 31, wid = tid >> 5;
    const int warpM = wid & 1, warpN = wid >> 1;
    const int bm = blockIdx.y * 128, bn = blockIdx.x * 128;

    const int aRow = tid >> 1, aCol = (tid & 1) * 8;
    const int bRow = tid >> 4, bCol = (tid & 15) * 8;
    const bool aValid = (bm + aRow) < M;
    const bool bValid = (bn + bCol) < N;

    float acc[4][4][4];
#pragma unroll
    for (int mt = 0; mt < 4; mt++)
#pragma unroll
        for (int nt = 0; nt < 4; nt++)
#pragma unroll
            for (int i = 0; i < 4; i++) acc[mt][nt][i] = 0.f;

    const int nk = K / 16, total = 3 * nk;
    const bf16* Ap = Ah; const bf16* Bp = Bh;
    int kc = 0, ph = 0;

    uint4 av = make_uint4(0, 0, 0, 0), bv = make_uint4(0, 0, 0, 0);
    if (aValid) av = *(const uint4*)(Ap + (size_t)(bm + aRow) * lda + aCol);
    if (bValid) bv = *(const uint4*)(Bp + (size_t)bRow * ldb + bn + bCol);

    const unsigned aBase = s2u(sA) + ((unsigned)((warpM * 64 + (lane & 15)) * APAD + (lane >> 4) * 8)) * 2u;
    const unsigned bBase = s2u(sB) + ((unsigned)((lane & 15) * BPAD + warpN * 32 + (lane >> 4) * 8)) * 2u;

    for (int it = 0; it < total; ++it) {
        *(uint4*)(sA + aRow * APAD + aCol) = av;
        *(uint4*)(sB + bRow * BPAD + bCol) = bv;
        __syncthreads();

        int nkc = kc + 1, nph = ph;
        const bf16 *An = Ap, *Bn = Bp;
        if (nkc == nk) { nkc = 0; nph = ph + 1; An = (nph == 2) ? Al : Ah; Bn = (nph == 1) ? Bl : Bh; }
        if (it + 1 < total) {
            if (aValid) av = *(const uint4*)(An + (size_t)(bm + aRow) * lda + nkc * 16 + aCol);
            if (bValid) bv = *(const uint4*)(Bn + (size_t)(nkc * 16 + bRow) * ldb + bn + bCol);
        }

        unsigned afr[4][4];
#pragma unroll
        for (int mt = 0; mt < 4; mt++) {
            unsigned addr = aBase + (unsigned)(mt * 16 * APAD * 2);
            asm volatile("ldmatrix.sync.aligned.m8n8.x4.shared.b16 {%0,%1,%2,%3}, [%4];"
                         : "=r"(afr[mt][0]), "=r"(afr[mt][1]), "=r"(afr[mt][2]), "=r"(afr[mt][3])
                         : "r"(addr));
        }
        unsigned bfr[4][2];
#pragma unroll
        for (int np = 0; np < 2; np++) {
            unsigned addr = bBase + (unsigned)(np * 16 * 2);
            unsigned r0, r1, r2, r3;
            asm volatile("ldmatrix.sync.aligned.m8n8.x4.trans.shared.b16 {%0,%1,%2,%3}, [%4];"
                         : "=r"(r0), "=r"(r1), "=r"(r2), "=r"(r3) : "r"(addr));
            bfr[np * 2 + 0][0] = r0; bfr[np * 2 + 0][1] = r1;
            bfr[np * 2 + 1][0] = r2; bfr[np * 2 + 1][1] = r3;
        }
#pragma unroll
        for (int mt = 0; mt < 4; mt++)
#pragma unroll
            for (int nt = 0; nt < 4; nt++) {
                asm volatile(
                    "mma.sync.aligned.m16n8k16.row.col.f32.bf16.bf16.f32 "
                    "{%0,%1,%2,%3}, {%4,%5,%6,%7}, {%8,%9}, {%0,%1,%2,%3};"
                    : "+f"(acc[mt][nt][0]), "+f"(acc[mt][nt][1]),
                      "+f"(acc[mt][nt][2]), "+f"(acc[mt][nt][3])
                    : "r"(afr[mt][0]), "r"(afr[mt][1]), "r"(afr[mt][2]), "r"(afr[mt][3]),
                      "r"(bfr[nt][0]), "r"(bfr[nt][1]));
            }
        __syncthreads();
        kc = nkc; ph = nph; Ap = An; Bp = Bn;
    }

    const int g = lane >> 2, t4 = lane & 3;
#pragma unroll
    for (int mt = 0; mt < 4; mt++) {
        int r0 = bm + warpM * 64 + mt * 16 + g;
#pragma unroll
        for (int nt = 0; nt < 4; nt++) {
            int c0 = bn + warpN * 32 + nt * 8 + t4 * 2;
            if (c0 >= N) continue;
            if (r0 < M) {
                float2* p = (float2*)(C + (size_t)r0 * ldc + c0);
                float2 v = make_float2(acc[mt][nt][0], acc[mt][nt][1]);
                if (accum) { float2 o = *p; v.x += o.x; v.y += o.y; }
                *p = v;
            }
            int r1 = r0 + 8;
            if (r1 < M) {
                float2* p = (float2*)(C + (size_t)r1 * ldc + c0);
                float2 v = make_float2(acc[mt][nt][2], acc[mt][nt][3]);
                if (accum) { float2 o = *p; v.x += o.x; v.y += o.y; }
                *p = v;
            }
        }
    }
}

static void run_bgemm(int M, int N, int K, const bf16* Ah, const bf16* Al, int lda,
                      const bf16* Bh, const bf16* Bl, int ldb,
                      float* C, int ldc, int accum) {
    dim3 grid((N + 127) / 128, (M + 127) / 128);
    bgemm_kernel<<<grid, 256>>>(M, N, K, Ah, Al, lda, Bh, Bl, ldb, C, ldc, accum);
}

// ------------------------- CSR prop -------------------------
__global__ void prop_kernel(const float4* __restrict__ src, int srcLd4,
                            float4* __restrict__ dst, int dstLd4, int D4,
                            float alpha, const float4* __restrict__ other, int otherLd4,
                            float beta, int accum,
                            const int* __restrict__ colptr, const int* __restrict__ erow,
                            const float* __restrict__ enorm) {
    int c = blockIdx.x, tid = threadIdx.x;
    __shared__ int sR[256];
    __shared__ float sW[256];
    int e0 = colptr[c], e1 = colptr[c + 1];
    float4 acc = make_float4(0, 0, 0, 0);
    for (int base = e0; base < e1; base += 256) {
        int cnt = min(256, e1 - base);
        for (int i = tid; i < cnt; i += blockDim.x) {
            sR[i] = erow[base + i];
            sW[i] = enorm[base + i];
        }
        __syncthreads();
        if (tid < D4) {
#pragma unroll 4
            for (int i = 0; i < cnt; i++) {
                float w = sW[i];
                float4 v = src[(size_t)sR[i] * srcLd4 + tid];
                acc.x += w * v.x; acc.y += w * v.y;
                acc.z += w * v.z; acc.w += w * v.w;
            }
        }
        __syncthreads();
    }
    if (tid < D4) {
        float4 r = make_float4(alpha * acc.x, alpha * acc.y, alpha * acc.z, alpha * acc.w);
        if (other) {
            float4 ov = other[(size_t)c * otherLd4 + tid];
            r.x += beta * ov.x; r.y += beta * ov.y; r.z += beta * ov.z; r.w += beta * ov.w;
        }
        size_t o = (size_t)c * dstLd4 + tid;
        if (accum) {
            float4 d = dst[o];
            r.x += d.x; r.y += d.y; r.z += d.z; r.w += d.w;
        }
        dst[o] = r;
    }
}

// ------------------------- batchnorm -------------------------
__global__ void bn_stats(const float* __restrict__ H, int ld, int C, int rows,
                         int rpb, float* __restrict__ gsum, float* __restrict__ gsq) {
    int c = blockIdx.x * blockDim.x + threadIdx.x;
    if (c >= C) return;
    int r0 = blockIdx.y * rpb, r1 = min(r0 + rpb, rows);
    float s = 0.f, q = 0.f;
    for (int r = r0; r < r1; r++) {
        float v = H[(size_t)r * ld + c];
        s += v; q += v * v;
    }
    atomicAdd(&gsum[c], s);
    atomicAdd(&gsq[c], q);
}

__global__ void bn_finalize(const float* __restrict__ gsum, const float* __restrict__ gsq,
                            const float* __restrict__ g, const float* __restrict__ beta,
                            float* __restrict__ s, float* __restrict__ t, int C, float invN) {
    int c = blockIdx.x * blockDim.x + threadIdx.x;
    if (c >= C) return;
    float mu = gsum[c] * invN;
    float var = gsq[c] * invN - mu * mu;
    float rs = rsqrtf(var + 1e-5f) * g[c];
    s[c] = rs;
    t[c] = beta[c] - mu * rs;
}

// BN + ReLU fused with bf16 hi/lo split (no fp32 writeback needed for layer 2)
__global__ void bn_apply_relu_split(const float2* __restrict__ H, const float* __restrict__ s,
                                    const float* __restrict__ t, bf162* __restrict__ hi,
                                    bf162* __restrict__ lo, size_t total2, int C2) {
    for (size_t i = blockIdx.x * (size_t)blockDim.x + threadIdx.x; i < total2;
         i += (size_t)gridDim.x * blockDim.x) {
        int c = (int)(i % C2) * 2;
        float2 v = H[i];
        float a = fmaxf(fmaf(v.x, s[c + 0], t[c + 0]), 0.f);
        float b = fmaxf(fmaf(v.y, s[c + 1], t[c + 1]), 0.f);
        bf16 ah = __float2bfloat16(a), bh = __float2bfloat16(b);
        bf162 h; h.x = ah; h.y = bh;
        bf162 l;
        l.x = __float2bfloat16(a - __bfloat162float(ah));
        l.y = __float2bfloat16(b - __bfloat162float(bh));
        hi[i] = h; lo[i] = l;
    }
}

// ---------------- final: BN2 + linear(300->10) + logsoftmax ----------------
__global__ void final_kernel(const float* __restrict__ Z, int ld,
                             const float* __restrict__ s, const float* __restrict__ t,
                             const float* __restrict__ Wl, const float* __restrict__ bl,
                             float* __restrict__ out, int rows) {
    __shared__ float sW[3000], ss[300], st[300], sb[16];
    int tid = threadIdx.x;
    for (int i = tid; i < 3000; i += 256) sW[i] = Wl[i];
    for (int i = tid; i < 300; i += 256) { ss[i] = s[i]; st[i] = t[i]; }
    if (tid < 10) sb[tid] = bl[tid];
    __syncthreads();
    int warp = tid >> 5, lane = tid & 31;
    int row = blockIdx.x * 8 + warp;
    if (row >= rows) return;
    float acc[10];
#pragma unroll
    for (int j = 0; j < 10; j++) acc[j] = 0.f;
    const float* zr = Z + (size_t)row * ld;
    for (int k = lane; k < 300; k += 32) {
        float h = fmaf(zr[k], ss[k], st[k]);
#pragma unroll
        for (int j = 0; j < 10; j++) acc[j] += h * sW[k * 10 + j];
    }
#pragma unroll
    for (int j = 0; j < 10; j++) {
#pragma unroll
        for (int o = 16; o > 0; o >>= 1) acc[j] += __shfl_xor_sync(0xffffffffu, acc[j], o);
        acc[j] += sb[j];
    }
    float m = acc[0];
#pragma unroll
    for (int j = 1; j < 10; j++) m = fmaxf(m, acc[j]);
    float sum = 0.f;
#pragma unroll
    for (int j = 0; j < 10; j++) sum += expf(acc[j] - m);
    float lse = m + logf(sum);
    if (lane < 10) out[(size_t)row * 10 + lane] = acc[lane] - lse;
}

// ------------------------- launch -------------------------
extern "C" void kernel_launch(void* const* d_in, const int* in_sizes, int n_in,
                              void* d_out, int out_size) {
    const float* x   = (const float*)d_in[0];
    const int*   eix = (const int*)  d_in[1];
    const float* ew  = (const float*)d_in[2];
    const float* W1a = (const float*)d_in[3];
    const float* W1b = (const float*)d_in[5];
    const float* W1c = (const float*)d_in[7];
    const float* g1  = (const float*)d_in[9];
    const float* be1 = (const float*)d_in[10];
    const float* W2a = (const float*)d_in[11];
    const float* W2b = (const float*)d_in[13];
    const float* W2c = (const float*)d_in[15];
    const float* g2  = (const float*)d_in[17];
    const float* be2 = (const float*)d_in[18];
    const float* Wl  = (const float*)d_in[19];
    const float* bl  = (const float*)d_in[20];
    float* out = (float*)d_out;

    unsigned char* base = nullptr;
    cudaGetSymbolAddress((void**)&base, g_scratch);

    float* deg  = (float*)(base + O_DEG);
    float* dis  = (float*)(base + O_DIS);
    float* nrm  = (float*)(base + O_NORM);
    int*   cnt  = (int*)  (base + O_CNT);
    int*   cptr = (int*)  (base + O_CPTR);
    int*   cur  = (int*)  (base + O_CUR);
    int*   erow = (int*)  (base + O_EROW);
    float* enrm = (float*)(base + O_ENRM);
    float* Tx1  = (float*)(base + O_TX1);
    float* Tx2  = (float*)(base + O_TX2);
    float* H1   = (float*)(base + O_H1);
    float* Z6   = (float*)(base + O_Z6);
    float* Q    = (float*)(base + O_Q);
    float* Wp1  = (float*)(base + O_WP1);
    float* Wp1b = (float*)(base + O_WP1B);
    float* Wp2  = (float*)(base + O_WP2);
    float* gsum = (float*)(base + O_SUM);
    float* gsq  = (float*)(base + O_SSQ);
    float* bnS  = (float*)(base + O_S);
    float* bnT  = (float*)(base + O_T);
    bf16* xh  = (bf16*)(base + O_XH);   bf16* xl  = (bf16*)(base + O_XL);
    bf16* t1h = (bf16*)(base + O_T1H);  bf16* t1l = (bf16*)(base + O_T1L);
    bf16* t2h = (bf16*)(base + O_T2H);  bf16* t2l = (bf16*)(base + O_T2L);
    bf16* h1h = (bf16*)(base + O_H1H);  bf16* h1l = (bf16*)(base + O_H1L);
    bf16* w1h = (bf16*)(base + O_W1H);  bf16* w1l = (bf16*)(base + O_W1L);
    bf16* w1bh= (bf16*)(base + O_W1BH); bf16* w1bl= (bf16*)(base + O_W1BL);
    bf16* w1ch= (bf16*)(base + O_W1CH); bf16* w1cl= (bf16*)(base + O_W1CL);
    bf16* w2h = (bf16*)(base + O_W2H);  bf16* w2l = (bf16*)(base + O_W2L);

    const int* row = eix;
    const int* col = eix + NEDGE;

    // --- front-loaded so the big GEMM is launch #6 (ncu -s 5 -c 1 target) ---
    split_kernel<<<4096, 256>>>((const float2*)x, (bf162*)xh, (bf162*)xl,
                                (size_t)NNODES * 256);
    pack_cols<<<256, 256>>>(Wp1, 1200, 0,   W1a, 400, 512);
    pack_cols<<<256, 256>>>(Wp1, 1200, 400, W1b, 400, 512);
    pack_cols<<<256, 256>>>(Wp1, 1200, 800, W1c, 400, 512);
    split_kernel<<<1024, 256>>>((const float2*)Wp1, (bf162*)w1h, (bf162*)w1l, 307200);
    run_bgemm(NNODES, 1200, 512, xh, xl, 512, w1h, w1l, 1200, H1, 1200, 0);   // launch #6

    // graph prep: degrees, norm, CSR-by-destination
    cudaMemsetAsync(deg, 0, (size_t)NNODES * 4);
    cudaMemsetAsync(cnt, 0, (size_t)NNODES * 4);
    deg_kernel<<<4096, 256>>>(row, ew, deg, NEDGE);
    dis_kernel<<<(NNODES + 255) / 256, 256>>>(deg, dis, NNODES);
    norm_cnt_kernel<<<4096, 256>>>(row, col, ew, dis, nrm, cnt, NEDGE);
    scan_kernel<<<1, 1024>>>(cnt, NNODES, cptr);
    cudaMemcpyAsync(cur, cptr, (size_t)NNODES * 4, cudaMemcpyDeviceToDevice);
    scatter_kernel<<<4096, 256>>>(row, col, nrm, cur, erow, enrm, NEDGE);

    // layer 1 remaining terms
    prop_kernel<<<NNODES, 128>>>((const float4*)x, 128, (float4*)Tx1, 128, 128,
                                 1.f, nullptr, 0, 0.f, 0, cptr, erow, enrm);
    split_kernel<<<4096, 256>>>((const float2*)Tx1, (bf162*)t1h, (bf162*)t1l,
                                (size_t)NNODES * 256);
    pack_cols<<<256, 256>>>(Wp1b, 800, 0,   W1b + 204800, 400, 512);
    pack_cols<<<256, 256>>>(Wp1b, 800, 400, W1c + 204800, 400, 512);
    split_kernel<<<1024, 256>>>((const float2*)Wp1b, (bf162*)w1bh, (bf162*)w1bl, 204800);
    run_bgemm(NNODES, 800, 512, t1h, t1l, 512, w1bh, w1bl, 800, H1 + 400, 1200, 1);

    prop_kernel<<<NNODES, 128>>>((const float4*)Tx1, 128, (float4*)Tx2, 128, 128,
                                 2.f, (const float4*)x, 128, -1.f, 0, cptr, erow, enrm);
    split_kernel<<<4096, 256>>>((const float2*)Tx2, (bf162*)t2h, (bf162*)t2l,
                                (size_t)NNODES * 256);
    split_kernel<<<1024, 256>>>((const float2*)(W1c + 409600), (bf162*)w1ch, (bf162*)w1cl,
                                102400);
    run_bgemm(NNODES, 400, 512, t2h, t2l, 512, w1ch, w1cl, 400, H1 + 800, 1200, 1);

    // BN1 + ReLU -> bf16 splits directly
    cudaMemsetAsync(gsum, 0, 1200 * 4);
    cudaMemsetAsync(gsq, 0, 1200 * 4);
    {
        dim3 g((1200 + 255) / 256, 20);
        bn_stats<<<g, 256>>>(H1, 1200, 1200, NNODES, 2500, gsum, gsq);
    }
    bn_finalize<<<(1200 + 255) / 256, 256>>>(gsum, gsq, g1, be1, bnS, bnT, 1200, 1.f / NNODES);
    bn_apply_relu_split<<<4096, 256>>>((const float2*)H1, bnS, bnT, (bf162*)h1h, (bf162*)h1l,
                                       (size_t)NNODES * 600, 600);

    // layer 2: GEMM-first (prop commutes with W)
    pack_cols<<<256, 256>>>(Wp2, 600, 0,   W2a,          100, 1200);
    pack_cols<<<256, 256>>>(Wp2, 600, 100, W2b,          100, 1200);
    pack_cols<<<256, 256>>>(Wp2, 600, 200, W2c,          100, 1200);
    pack_cols<<<256, 256>>>(Wp2, 600, 300, W2b + 120000, 100, 1200);
    pack_cols<<<256, 256>>>(Wp2, 600, 400, W2c + 120000, 100, 1200);
    pack_cols<<<256, 256>>>(Wp2, 600, 500, W2c + 240000, 100, 1200);
    split_kernel<<<1024, 256>>>((const float2*)Wp2, (bf162*)w2h, (bf162*)w2l, 360000);
    run_bgemm(NNODES, 600, 1200, h1h, h1l, 1200, w2h, w2l, 600, Z6, 600, 0);

    // Z6[:,100:300] += prop(Z6[:,300:500])
    prop_kernel<<<NNODES, 64>>>((const float4*)(Z6 + 300), 150, (float4*)(Z6 + 100), 150, 50,
                                1.f, nullptr, 0, 0.f, 1, cptr, erow, enrm);
    // Q = prop(Z6[:,500:600])
    prop_kernel<<<NNODES, 32>>>((const float4*)(Z6 + 500), 150, (float4*)Q, 25, 25,
                                1.f, nullptr, 0, 0.f, 0, cptr, erow, enrm);
    // Z6[:,200:300] += 2*prop(Q) - Z6[:,500:600]
    prop_kernel<<<NNODES, 32>>>((const float4*)Q, 25, (float4*)(Z6 + 200), 150, 25,
                                2.f, (const float4*)(Z6 + 500), 150, -1.f, 1, cptr, erow, enrm);

    // BN2 stats
    cudaMemsetAsync(gsum, 0, 300 * 4);
    cudaMemsetAsync(gsq, 0, 300 * 4);
    {
        dim3 g((300 + 255) / 256, 20);
        bn_stats<<<g, 256>>>(Z6, 600, 300, NNODES, 2500, gsum, gsq);
    }
    bn_finalize<<<(300 + 255) / 256, 256>>>(gsum, gsq, g2, be2, bnS, bnT, 300, 1.f / NNODES);

    // fused BN2 + linear + log_softmax
    final_kernel<<<(NNODES + 7) / 8, 256>>>(Z6, 600, bnS, bnT, Wl, bl, out, NNODES);
}

// round 14
// speedup vs baseline: 1.6342x; 1.1901x over previous
#include <cuda_runtime.h>
#include <cuda_bf16.h>

#define NNODES 50000
#define NEDGE  1600000

using bf16 = __nv_bfloat16;
using bf162 = __nv_bfloat162;

constexpr size_t AL(size_t x) { return (x + 255) & ~(size_t)255; }
constexpr size_t O_DEG  = 0;
constexpr size_t O_DIS  = AL(O_DEG  + (size_t)NNODES*4);
constexpr size_t O_NORM = AL(O_DIS  + (size_t)NNODES*4);
constexpr size_t O_CNT  = AL(O_NORM + (size_t)NEDGE*4);
constexpr size_t O_CPTR = AL(O_CNT  + (size_t)NNODES*4);
constexpr size_t O_CUR  = AL(O_CPTR + (size_t)(NNODES+1)*4);
constexpr size_t O_EROW = AL(O_CUR  + (size_t)NNODES*4);
constexpr size_t O_ENRM = AL(O_EROW + (size_t)NEDGE*4);
constexpr size_t O_TX1  = AL(O_ENRM + (size_t)NEDGE*4);
constexpr size_t O_TX2  = AL(O_TX1  + (size_t)NNODES*512*4);
constexpr size_t O_H1   = AL(O_TX2  + (size_t)NNODES*512*4);
constexpr size_t O_Z6   = AL(O_H1   + (size_t)NNODES*1200*4);
constexpr size_t O_Q    = AL(O_Z6   + (size_t)NNODES*600*4);
constexpr size_t O_WP1  = AL(O_Q    + (size_t)NNODES*100*4);
constexpr size_t O_WP1B = AL(O_WP1  + (size_t)512*1200*4);
constexpr size_t O_WPC  = AL(O_WP1B + (size_t)512*800*4);
constexpr size_t O_WP2  = AL(O_WPC  + (size_t)512*400*4);
constexpr size_t O_SUM  = AL(O_WP2  + (size_t)1200*600*4);
constexpr size_t O_SSQ  = AL(O_SUM  + (size_t)1200*4);
constexpr size_t O_S    = AL(O_SSQ  + (size_t)1200*4);
constexpr size_t O_T    = AL(O_S    + (size_t)1200*4);
constexpr size_t O_XH  = AL(O_T   + (size_t)1200*4);
constexpr size_t O_XL  = AL(O_XH  + (size_t)NNODES*512*2);
constexpr size_t O_T1H = AL(O_XL  + (size_t)NNODES*512*2);
constexpr size_t O_T1L = AL(O_T1H + (size_t)NNODES*512*2);
constexpr size_t O_T2H = AL(O_T1L + (size_t)NNODES*512*2);
constexpr size_t O_T2L = AL(O_T2H + (size_t)NNODES*512*2);
constexpr size_t O_H1H = AL(O_T2L + (size_t)NNODES*512*2);
constexpr size_t O_H1L = AL(O_H1H + (size_t)NNODES*1200*2);
constexpr size_t O_W1H = AL(O_H1L + (size_t)NNODES*1200*2);
constexpr size_t O_W1L = AL(O_W1H + (size_t)512*1200*2);
constexpr size_t O_W1BH= AL(O_W1L + (size_t)512*1200*2);
constexpr size_t O_W1BL= AL(O_W1BH+ (size_t)512*800*2);
constexpr size_t O_W1CH= AL(O_W1BL+ (size_t)512*800*2);
constexpr size_t O_W1CL= AL(O_W1CH+ (size_t)512*400*2);
constexpr size_t O_W2H = AL(O_W1CL+ (size_t)512*400*2);
constexpr size_t O_W2L = AL(O_W2H + (size_t)1200*600*2);
constexpr size_t SCRATCH_BYTES = AL(O_W2L + (size_t)1200*600*2);

__device__ __align__(256) unsigned char g_scratch[SCRATCH_BYTES];

// ------------------------- graph prep -------------------------
__global__ void deg_kernel(const int* __restrict__ row, const float* __restrict__ w,
                           float* __restrict__ deg, int E) {
    for (int e = blockIdx.x * blockDim.x + threadIdx.x; e < E; e += gridDim.x * blockDim.x)
        atomicAdd(&deg[row[e]], w[e]);
}

__global__ void dis_kernel(const float* __restrict__ deg, float* __restrict__ dis, int n) {
    int i = blockIdx.x * blockDim.x + threadIdx.x;
    if (i < n) { float d = deg[i]; dis[i] = (d > 0.f) ? rsqrtf(d) : 0.f; }
}

__global__ void norm_cnt_kernel(const int* __restrict__ row, const int* __restrict__ col,
                                const float* __restrict__ w, const float* __restrict__ dis,
                                float* __restrict__ nrm, int* __restrict__ cnt, int E) {
    for (int e = blockIdx.x * blockDim.x + threadIdx.x; e < E; e += gridDim.x * blockDim.x) {
        int r = row[e], c = col[e];
        nrm[e] = -dis[r] * w[e] * dis[c];
        atomicAdd(&cnt[c], 1);
    }
}

__global__ void scan_kernel(const int* __restrict__ cnt, int n, int* __restrict__ colptr) {
    __shared__ int part[1024];
    int tid = threadIdx.x;
    int per = (n + 1023) / 1024;
    int s0 = tid * per, s1 = min(s0 + per, n);
    int s = 0;
    for (int i = s0; i < s1; i++) s += cnt[i];
    part[tid] = s;
    __syncthreads();
    for (int off = 1; off < 1024; off <<= 1) {
        int v = (tid >= off) ? part[tid - off] : 0;
        __syncthreads();
        part[tid] += v;
        __syncthreads();
    }
    int prefix = (tid == 0) ? 0 : part[tid - 1];
    for (int i = s0; i < s1; i++) { colptr[i] = prefix; prefix += cnt[i]; }
    if (tid == 0) colptr[n] = part[1023];
}

__global__ void scatter_kernel(const int* __restrict__ row, const int* __restrict__ col,
                               const float* __restrict__ nrm, int* __restrict__ cursor,
                               int* __restrict__ erow, float* __restrict__ enorm, int E) {
    for (int e = blockIdx.x * blockDim.x + threadIdx.x; e < E; e += gridDim.x * blockDim.x) {
        int c = col[e];
        int p = atomicAdd(&cursor[c], 1);
        erow[p] = row[e];
        enorm[p] = nrm[e];
    }
}

// ---------------- transposed weight packing + bf16 split ----------------
// dst[(nOff + c) * ldk + r] = src[r * srcCols + c]   (W [K,C] -> Wt [N,K])
__global__ void pack_colsT(float* __restrict__ dst, int ldk, int nOff,
                           const float* __restrict__ src, int srcCols, int rowsK) {
    int total = rowsK * srcCols;
    for (int i = blockIdx.x * blockDim.x + threadIdx.x; i < total; i += gridDim.x * blockDim.x) {
        int r = i / srcCols, c = i - r * srcCols;
        dst[(size_t)(nOff + c) * ldk + r] = src[i];
    }
}

__global__ void split_kernel(const float2* __restrict__ src, bf162* __restrict__ hi,
                             bf162* __restrict__ lo, size_t n2) {
    for (size_t i = blockIdx.x * (size_t)blockDim.x + threadIdx.x; i < n2;
         i += (size_t)gridDim.x * blockDim.x) {
        float2 v = src[i];
        bf16 ax = __float2bfloat16(v.x), ay = __float2bfloat16(v.y);
        bf162 h; h.x = ax; h.y = ay;
        bf162 l;
        l.x = __float2bfloat16(v.x - __bfloat162float(ax));
        l.y = __float2bfloat16(v.y - __bfloat162float(ay));
        hi[i] = h; lo[i] = l;
    }
}

// ---------------- legacy-tensor split-GEMM (mma.sync, pipelined) ----------------
// C[M,N] (+)= Ah*Bt_h^T + Ah*Bt_l^T + Al*Bt_h^T, fp32 accum.
// A: [M,K] bf16 row-major. Bt: [N,K] bf16 row-major. K%16==0.

__device__ __forceinline__ void cp16(unsigned dst, const void* src, bool v) {
    int sz = v ? 16 : 0;
    asm volatile("cp.async.cg.shared.global [%0], [%1], 16, %2;"
                 :: "r"(dst), "l"(src), "r"(sz));
}

#define TSTR 24                       // tile row stride in bf16 (48B)
#define TILE_B (128 * TSTR * 2)       // 6144 bytes per tile
#define STAGE_B (4 * TILE_B)          // Ah, Al, Bh, Bl

__global__ __launch_bounds__(256, 2)
void bgemm_kernel(int M, int N, int K,
                  const bf16* __restrict__ Ah, const bf16* __restrict__ Al, int lda,
                  const bf16* __restrict__ Bh, const bf16* __restrict__ Bl, int ldb,
                  float* __restrict__ C, int ldc, int accum) {
    __shared__ __align__(16) unsigned char sm[2 * STAGE_B];
    const unsigned smb = (unsigned)__cvta_generic_to_shared(sm);

    const int tid = threadIdx.x, lane = tid & 31, wid = tid >> 5;
    const int warpM = wid & 1, warpN = wid >> 1;
    const int bm = blockIdx.y * 128, bn = blockIdx.x * 128;

    // loader mapping: each thread owns one 16B chunk per tile
    const int lRow = tid >> 1, lK8 = (tid & 1) * 8;
    const unsigned lOff = (unsigned)(lRow * TSTR + lK8) * 2u;
    const bool av = (bm + lRow) < M;
    const bool bv = (bn + lRow) < N;
    const size_t aRowOff = (size_t)min(bm + lRow, M - 1) * lda + lK8;
    const size_t bRowOff = (size_t)min(bn + lRow, N - 1) * ldb + lK8;

    // ldmatrix lane offsets (bytes within tile)
    const unsigned aLd = (unsigned)(((warpM * 64 + (lane & 15)) * TSTR + (lane >> 4) * 8) * 2);
    const unsigned bLd = (unsigned)(((warpN * 32 + (lane & 7)) * TSTR + ((lane >> 3) & 1) * 8) * 2);

    float acc[4][4][4];
#pragma unroll
    for (int mt = 0; mt < 4; mt++)
#pragma unroll
        for (int nt = 0; nt < 4; nt++)
#pragma unroll
            for (int i = 0; i < 4; i++) acc[mt][nt][i] = 0.f;

    const int nk = K / 16;

    auto prefetch = [&](int stage, int ch) {
        unsigned sb = smb + stage * STAGE_B;
        size_t ko = (size_t)(ch * 16);
        cp16(sb + 0 * TILE_B + lOff, Ah + aRowOff + ko, av);
        cp16(sb + 1 * TILE_B + lOff, Al + aRowOff + ko, av);
        cp16(sb + 2 * TILE_B + lOff, Bh + bRowOff + ko, bv);
        cp16(sb + 3 * TILE_B + lOff, Bl + bRowOff + ko, bv);
    };

    prefetch(0, 0);
    asm volatile("cp.async.commit_group;" ::: "memory");

    for (int it = 0; it < nk; ++it) {
        if (it + 1 < nk) prefetch((it + 1) & 1, it + 1);
        asm volatile("cp.async.commit_group;" ::: "memory");
        asm volatile("cp.async.wait_group 1;" ::: "memory");
        __syncthreads();

        unsigned sb = smb + (it & 1) * STAGE_B;
        unsigned a4[4][4], bh2[4][2], bl2[4][2];
#pragma unroll
        for (int mt = 0; mt < 4; mt++) {
            unsigned addr = sb + 0 * TILE_B + aLd + (unsigned)(mt * 16 * TSTR * 2);
            asm volatile("ldmatrix.sync.aligned.m8n8.x4.shared.b16 {%0,%1,%2,%3}, [%4];"
                         : "=r"(a4[mt][0]), "=r"(a4[mt][1]), "=r"(a4[mt][2]), "=r"(a4[mt][3])
                         : "r"(addr));
        }
#pragma unroll
        for (int nt = 0; nt < 4; nt++) {
            unsigned addr = sb + 2 * TILE_B + bLd + (unsigned)(nt * 8 * TSTR * 2);
            asm volatile("ldmatrix.sync.aligned.m8n8.x2.shared.b16 {%0,%1}, [%2];"
                         : "=r"(bh2[nt][0]), "=r"(bh2[nt][1]) : "r"(addr));
        }
#pragma unroll
        for (int nt = 0; nt < 4; nt++) {
            unsigned addr = sb + 3 * TILE_B + bLd + (unsigned)(nt * 8 * TSTR * 2);
            asm volatile("ldmatrix.sync.aligned.m8n8.x2.shared.b16 {%0,%1}, [%2];"
                         : "=r"(bl2[nt][0]), "=r"(bl2[nt][1]) : "r"(addr));
        }
#define MMA(ar, br)                                                              \
        asm volatile("mma.sync.aligned.m16n8k16.row.col.f32.bf16.bf16.f32 "      \
            "{%0,%1,%2,%3}, {%4,%5,%6,%7}, {%8,%9}, {%0,%1,%2,%3};"              \
            : "+f"(acc[mt][nt][0]), "+f"(acc[mt][nt][1]),                        \
              "+f"(acc[mt][nt][2]), "+f"(acc[mt][nt][3])                         \
            : "r"((ar)[0]), "r"((ar)[1]), "r"((ar)[2]), "r"((ar)[3]),            \
              "r"((br)[0]), "r"((br)[1]))
#pragma unroll
        for (int mt = 0; mt < 4; mt++)
#pragma unroll
            for (int nt = 0; nt < 4; nt++) { MMA(a4[mt], bh2[nt]); }
#pragma unroll
        for (int mt = 0; mt < 4; mt++)
#pragma unroll
            for (int nt = 0; nt < 4; nt++) { MMA(a4[mt], bl2[nt]); }
        // overwrite A-hi frags with A-lo
#pragma unroll
        for (int mt = 0; mt < 4; mt++) {
            unsigned addr = sb + 1 * TILE_B + aLd + (unsigned)(mt * 16 * TSTR * 2);
            asm volatile("ldmatrix.sync.aligned.m8n8.x4.shared.b16 {%0,%1,%2,%3}, [%4];"
                         : "=r"(a4[mt][0]), "=r"(a4[mt][1]), "=r"(a4[mt][2]), "=r"(a4[mt][3])
                         : "r"(addr));
        }
#pragma unroll
        for (int mt = 0; mt < 4; mt++)
#pragma unroll
            for (int nt = 0; nt < 4; nt++) { MMA(a4[mt], bh2[nt]); }
#undef MMA
        __syncthreads();
    }

    const int g = lane >> 2, t4 = lane & 3;
#pragma unroll
    for (int mt = 0; mt < 4; mt++) {
        int r0 = bm + warpM * 64 + mt * 16 + g;
#pragma unroll
        for (int nt = 0; nt < 4; nt++) {
            int c0 = bn + warpN * 32 + nt * 8 + t4 * 2;
            if (c0 >= N) continue;
            if (r0 < M) {
                float2* p = (float2*)(C + (size_t)r0 * ldc + c0);
                float2 v = make_float2(acc[mt][nt][0], acc[mt][nt][1]);
                if (accum) { float2 o = *p; v.x += o.x; v.y += o.y; }
                *p = v;
            }
            int r1 = r0 + 8;
            if (r1 < M) {
                float2* p = (float2*)(C + (size_t)r1 * ldc + c0);
                float2 v = make_float2(acc[mt][nt][2], acc[mt][nt][3]);
                if (accum) { float2 o = *p; v.x += o.x; v.y += o.y; }
                *p = v;
            }
        }
    }
}

static void run_bgemm(int M, int N, int K, const bf16* Ah, const bf16* Al, int lda,
                      const bf16* Bh, const bf16* Bl, int ldb,
                      float* C, int ldc, int accum) {
    dim3 grid((N + 127) / 128, (M + 127) / 128);
    bgemm_kernel<<<grid, 256>>>(M, N, K, Ah, Al, lda, Bh, Bl, ldb, C, ldc, accum);
}

// ------------------------- CSR prop -------------------------
__global__ void prop_kernel(const float4* __restrict__ src, int srcLd4,
                            float4* __restrict__ dst, int dstLd4, int D4,
                            float alpha, const float4* __restrict__ other, int otherLd4,
                            float beta, int accum,
                            const int* __restrict__ colptr, const int* __restrict__ erow,
                            const float* __restrict__ enorm) {
    int c = blockIdx.x, tid = threadIdx.x;
    __shared__ int sR[256];
    __shared__ float sW[256];
    int e0 = colptr[c], e1 = colptr[c + 1];
    float4 acc = make_float4(0, 0, 0, 0);
    for (int base = e0; base < e1; base += 256) {
        int cnt = min(256, e1 - base);
        for (int i = tid; i < cnt; i += blockDim.x) {
            sR[i] = erow[base + i];
            sW[i] = enorm[base + i];
        }
        __syncthreads();
        if (tid < D4) {
#pragma unroll 4
            for (int i = 0; i < cnt; i++) {
                float w = sW[i];
                float4 v = src[(size_t)sR[i] * srcLd4 + tid];
                acc.x += w * v.x; acc.y += w * v.y;
                acc.z += w * v.z; acc.w += w * v.w;
            }
        }
        __syncthreads();
    }
    if (tid < D4) {
        float4 r = make_float4(alpha * acc.x, alpha * acc.y, alpha * acc.z, alpha * acc.w);
        if (other) {
            float4 ov = other[(size_t)c * otherLd4 + tid];
            r.x += beta * ov.x; r.y += beta * ov.y; r.z += beta * ov.z; r.w += beta * ov.w;
        }
        size_t o = (size_t)c * dstLd4 + tid;
        if (accum) {
            float4 d = dst[o];
            r.x += d.x; r.y += d.y; r.z += d.z; r.w += d.w;
        }
        dst[o] = r;
    }
}

// ------------------------- batchnorm -------------------------
__global__ void bn_stats(const float* __restrict__ H, int ld, int C, int rows,
                         int rpb, float* __restrict__ gsum, float* __restrict__ gsq) {
    int c = blockIdx.x * blockDim.x + threadIdx.x;
    if (c >= C) return;
    int r0 = blockIdx.y * rpb, r1 = min(r0 + rpb, rows);
    float s = 0.f, q = 0.f;
    for (int r = r0; r < r1; r++) {
        float v = H[(size_t)r * ld + c];
        s += v; q += v * v;
    }
    atomicAdd(&gsum[c], s);
    atomicAdd(&gsq[c], q);
}

__global__ void bn_finalize(const float* __restrict__ gsum, const float* __restrict__ gsq,
                            const float* __restrict__ g, const float* __restrict__ beta,
                            float* __restrict__ s, float* __restrict__ t, int C, float invN) {
    int c = blockIdx.x * blockDim.x + threadIdx.x;
    if (c >= C) return;
    float mu = gsum[c] * invN;
    float var = gsq[c] * invN - mu * mu;
    float rs = rsqrtf(var + 1e-5f) * g[c];
    s[c] = rs;
    t[c] = beta[c] - mu * rs;
}

__global__ void bn_apply_relu_split(const float2* __restrict__ H, const float* __restrict__ s,
                                    const float* __restrict__ t, bf162* __restrict__ hi,
                                    bf162* __restrict__ lo, size_t total2, int C2) {
    for (size_t i = blockIdx.x * (size_t)blockDim.x + threadIdx.x; i < total2;
         i += (size_t)gridDim.x * blockDim.x) {
        int c = (int)(i % C2) * 2;
        float2 v = H[i];
        float a = fmaxf(fmaf(v.x, s[c + 0], t[c + 0]), 0.f);
        float b = fmaxf(fmaf(v.y, s[c + 1], t[c + 1]), 0.f);
        bf16 ah = __float2bfloat16(a), bh = __float2bfloat16(b);
        bf162 h; h.x = ah; h.y = bh;
        bf162 l;
        l.x = __float2bfloat16(a - __bfloat162float(ah));
        l.y = __float2bfloat16(b - __bfloat162float(bh));
        hi[i] = h; lo[i] = l;
    }
}

// ---------------- final: BN2 + linear(300->10) + logsoftmax ----------------
__global__ void final_kernel(const float* __restrict__ Z, int ld,
                             const float* __restrict__ s, const float* __restrict__ t,
                             const float* __restrict__ Wl, const float* __restrict__ bl,
                             float* __restrict__ out, int rows) {
    __shared__ float sW[3000], ss[300], st[300], sb[16];
    int tid = threadIdx.x;
    for (int i = tid; i < 3000; i += 256) sW[i] = Wl[i];
    for (int i = tid; i < 300; i += 256) { ss[i] = s[i]; st[i] = t[i]; }
    if (tid < 10) sb[tid] = bl[tid];
    __syncthreads();
    int warp = tid >> 5, lane = tid & 31;
    int row = blockIdx.x * 8 + warp;
    if (row >= rows) return;
    float acc[10];
#pragma unroll
    for (int j = 0; j < 10; j++) acc[j] = 0.f;
    const float* zr = Z + (size_t)row * ld;
    for (int k = lane; k < 300; k += 32) {
        float h = fmaf(zr[k], ss[k], st[k]);
#pragma unroll
        for (int j = 0; j < 10; j++) acc[j] += h * sW[k * 10 + j];
    }
#pragma unroll
    for (int j = 0; j < 10; j++) {
#pragma unroll
        for (int o = 16; o > 0; o >>= 1) acc[j] += __shfl_xor_sync(0xffffffffu, acc[j], o);
        acc[j] += sb[j];
    }
    float m = acc[0];
#pragma unroll
    for (int j = 1; j < 10; j++) m = fmaxf(m, acc[j]);
    float sum = 0.f;
#pragma unroll
    for (int j = 0; j < 10; j++) sum += expf(acc[j] - m);
    float lse = m + logf(sum);
    if (lane < 10) out[(size_t)row * 10 + lane] = acc[lane] - lse;
}

// ------------------------- launch -------------------------
extern "C" void kernel_launch(void* const* d_in, const int* in_sizes, int n_in,
                              void* d_out, int out_size) {
    const float* x   = (const float*)d_in[0];
    const int*   eix = (const int*)  d_in[1];
    const float* ew  = (const float*)d_in[2];
    const float* W1a = (const float*)d_in[3];
    const float* W1b = (const float*)d_in[5];
    const float* W1c = (const float*)d_in[7];
    const float* g1  = (const float*)d_in[9];
    const float* be1 = (const float*)d_in[10];
    const float* W2a = (const float*)d_in[11];
    const float* W2b = (const float*)d_in[13];
    const float* W2c = (const float*)d_in[15];
    const float* g2  = (const float*)d_in[17];
    const float* be2 = (const float*)d_in[18];
    const float* Wl  = (const float*)d_in[19];
    const float* bl  = (const float*)d_in[20];
    float* out = (float*)d_out;

    unsigned char* base = nullptr;
    cudaGetSymbolAddress((void**)&base, g_scratch);

    float* deg  = (float*)(base + O_DEG);
    float* dis  = (float*)(base + O_DIS);
    float* nrm  = (float*)(base + O_NORM);
    int*   cnt  = (int*)  (base + O_CNT);
    int*   cptr = (int*)  (base + O_CPTR);
    int*   cur  = (int*)  (base + O_CUR);
    int*   erow = (int*)  (base + O_EROW);
    float* enrm = (float*)(base + O_ENRM);
    float* Tx1  = (float*)(base + O_TX1);
    float* Tx2  = (float*)(base + O_TX2);
    float* H1   = (float*)(base + O_H1);
    float* Z6   = (float*)(base + O_Z6);
    float* Q    = (float*)(base + O_Q);
    float* Wt1  = (float*)(base + O_WP1);
    float* Wt1b = (float*)(base + O_WP1B);
    float* Wt1c = (float*)(base + O_WPC);
    float* Wt2  = (float*)(base + O_WP2);
    float* gsum = (float*)(base + O_SUM);
    float* gsq  = (float*)(base + O_SSQ);
    float* bnS  = (float*)(base + O_S);
    float* bnT  = (float*)(base + O_T);
    bf16* xh  = (bf16*)(base + O_XH);   bf16* xl  = (bf16*)(base + O_XL);
    bf16* t1h = (bf16*)(base + O_T1H);  bf16* t1l = (bf16*)(base + O_T1L);
    bf16* t2h = (bf16*)(base + O_T2H);  bf16* t2l = (bf16*)(base + O_T2L);
    bf16* h1h = (bf16*)(base + O_H1H);  bf16* h1l = (bf16*)(base + O_H1L);
    bf16* w1h = (bf16*)(base + O_W1H);  bf16* w1l = (bf16*)(base + O_W1L);
    bf16* w1bh= (bf16*)(base + O_W1BH); bf16* w1bl= (bf16*)(base + O_W1BL);
    bf16* w1ch= (bf16*)(base + O_W1CH); bf16* w1cl= (bf16*)(base + O_W1CL);
    bf16* w2h = (bf16*)(base + O_W2H);  bf16* w2l = (bf16*)(base + O_W2L);

    const int* row = eix;
    const int* col = eix + NEDGE;

    // splits + transposed weight packing
    split_kernel<<<4096, 256>>>((const float2*)x, (bf162*)xh, (bf162*)xl,
                                (size_t)NNODES * 256);
    pack_colsT<<<256, 256>>>(Wt1, 512, 0,   W1a, 400, 512);
    pack_colsT<<<256, 256>>>(Wt1, 512, 400, W1b, 400, 512);
    pack_colsT<<<256, 256>>>(Wt1, 512, 800, W1c, 400, 512);
    split_kernel<<<1024, 256>>>((const float2*)Wt1, (bf162*)w1h, (bf162*)w1l, 307200);
    run_bgemm(NNODES, 1200, 512, xh, xl, 512, w1h, w1l, 512, H1, 1200, 0);

    // graph prep: degrees, norm, CSR-by-destination
    cudaMemsetAsync(deg, 0, (size_t)NNODES * 4);
    cudaMemsetAsync(cnt, 0, (size_t)NNODES * 4);
    deg_kernel<<<4096, 256>>>(row, ew, deg, NEDGE);
    dis_kernel<<<(NNODES + 255) / 256, 256>>>(deg, dis, NNODES);
    norm_cnt_kernel<<<4096, 256>>>(row, col, ew, dis, nrm, cnt, NEDGE);
    scan_kernel<<<1, 1024>>>(cnt, NNODES, cptr);
    cudaMemcpyAsync(cur, cptr, (size_t)NNODES * 4, cudaMemcpyDeviceToDevice);
    scatter_kernel<<<4096, 256>>>(row, col, nrm, cur, erow, enrm, NEDGE);

    // layer 1 remaining terms
    prop_kernel<<<NNODES, 128>>>((const float4*)x, 128, (float4*)Tx1, 128, 128,
                                 1.f, nullptr, 0, 0.f, 0, cptr, erow, enrm);
    split_kernel<<<4096, 256>>>((const float2*)Tx1, (bf162*)t1h, (bf162*)t1l,
                                (size_t)NNODES * 256);
    pack_colsT<<<256, 256>>>(Wt1b, 512, 0,   W1b + 204800, 400, 512);
    pack_colsT<<<256, 256>>>(Wt1b, 512, 400, W1c + 204800, 400, 512);
    split_kernel<<<1024, 256>>>((const float2*)Wt1b, (bf162*)w1bh, (bf162*)w1bl, 204800);
    run_bgemm(NNODES, 800, 512, t1h, t1l, 512, w1bh, w1bl, 512, H1 + 400, 1200, 1);

    prop_kernel<<<NNODES, 128>>>((const float4*)Tx1, 128, (float4*)Tx2, 128, 128,
                                 2.f, (const float4*)x, 128, -1.f, 0, cptr, erow, enrm);
    split_kernel<<<4096, 256>>>((const float2*)Tx2, (bf162*)t2h, (bf162*)t2l,
                                (size_t)NNODES * 256);
    pack_colsT<<<256, 256>>>(Wt1c, 512, 0, W1c + 409600, 400, 512);
    split_kernel<<<1024, 256>>>((const float2*)Wt1c, (bf162*)w1ch, (bf162*)w1cl, 102400);
    run_bgemm(NNODES, 400, 512, t2h, t2l, 512, w1ch, w1cl, 512, H1 + 800, 1200, 1);

    // BN1 + ReLU -> bf16 splits directly
    cudaMemsetAsync(gsum, 0, 1200 * 4);
    cudaMemsetAsync(gsq, 0, 1200 * 4);
    {
        dim3 g((1200 + 255) / 256, 20);
        bn_stats<<<g, 256>>>(H1, 1200, 1200, NNODES, 2500, gsum, gsq);
    }
    bn_finalize<<<(1200 + 255) / 256, 256>>>(gsum, gsq, g1, be1, bnS, bnT, 1200, 1.f / NNODES);
    bn_apply_relu_split<<<4096, 256>>>((const float2*)H1, bnS, bnT, (bf162*)h1h, (bf162*)h1l,
                                       (size_t)NNODES * 600, 600);

    // layer 2: GEMM-first (prop commutes with W)
    pack_colsT<<<256, 256>>>(Wt2, 1200, 0,   W2a,          100, 1200);
    pack_colsT<<<256, 256>>>(Wt2, 1200, 100, W2b,          100, 1200);
    pack_colsT<<<256, 256>>>(Wt2, 1200, 200, W2c,          100, 1200);
    pack_colsT<<<256, 256>>>(Wt2, 1200, 300, W2b + 120000, 100, 1200);
    pack_colsT<<<256, 256>>>(Wt2, 1200, 400, W2c + 120000, 100, 1200);
    pack_colsT<<<256, 256>>>(Wt2, 1200, 500, W2c + 240000, 100, 1200);
    split_kernel<<<1024, 256>>>((const float2*)Wt2, (bf162*)w2h, (bf162*)w2l, 360000);
    run_bgemm(NNODES, 600, 1200, h1h, h1l, 1200, w2h, w2l, 1200, Z6, 600, 0);

    // Z6[:,100:300] += prop(Z6[:,300:500])
    prop_kernel<<<NNODES, 64>>>((const float4*)(Z6 + 300), 150, (float4*)(Z6 + 100), 150, 50,
                                1.f, nullptr, 0, 0.f, 1, cptr, erow, enrm);
    // Q = prop(Z6[:,500:600])
    prop_kernel<<<NNODES, 32>>>((const float4*)(Z6 + 500), 150, (float4*)Q, 25, 25,
                                1.f, nullptr, 0, 0.f, 0, cptr, erow, enrm);
    // Z6[:,200:300] += 2*prop(Q) - Z6[:,500:600]
    prop_kernel<<<NNODES, 32>>>((const float4*)Q, 25, (float4*)(Z6 + 200), 150, 25,
                                2.f, (const float4*)(Z6 + 500), 150, -1.f, 1, cptr, erow, enrm);

    // BN2 stats
    cudaMemsetAsync(gsum, 0, 300 * 4);
    cudaMemsetAsync(gsq, 0, 300 * 4);
    {
        dim3 g((300 + 255) / 256, 20);
        bn_stats<<<g, 256>>>(Z6, 600, 300, NNODES, 2500, gsum, gsq);
    }
    bn_finalize<<<(300 + 255) / 256, 256>>>(gsum, gsq, g2, be2, bnS, bnT, 300, 1.f / NNODES);

    // fused BN2 + linear + log_softmax
    final_kernel<<<(NNODES + 7) / 8, 256>>>(Z6, 600, bnS, bnT, Wl, bl, out, NNODES);
}

// round 15
// speedup vs baseline: 1.6356x; 1.0008x over previous
#include <cuda_runtime.h>
#include <cuda_bf16.h>

#define NNODES 50000
#define NEDGE  1600000

using bf16 = __nv_bfloat16;
using bf162 = __nv_bfloat162;

constexpr size_t AL(size_t x) { return (x + 255) & ~(size_t)255; }
constexpr size_t O_DEG  = 0;
constexpr size_t O_DIS  = AL(O_DEG  + (size_t)NNODES*4);
constexpr size_t O_NORM = AL(O_DIS  + (size_t)NNODES*4);
constexpr size_t O_CNT  = AL(O_NORM + (size_t)NEDGE*4);
constexpr size_t O_CPTR = AL(O_CNT  + (size_t)NNODES*4);
constexpr size_t O_CUR  = AL(O_CPTR + (size_t)(NNODES+1)*4);
constexpr size_t O_EROW = AL(O_CUR  + (size_t)NNODES*4);
constexpr size_t O_ENRM = AL(O_EROW + (size_t)NEDGE*4);
constexpr size_t O_TX1  = AL(O_ENRM + (size_t)NEDGE*4);
constexpr size_t O_TX2  = AL(O_TX1  + (size_t)NNODES*512*4);
constexpr size_t O_H1   = AL(O_TX2  + (size_t)NNODES*512*4);
constexpr size_t O_Z6   = AL(O_H1   + (size_t)NNODES*1200*4);
constexpr size_t O_Q    = AL(O_Z6   + (size_t)NNODES*600*4);
constexpr size_t O_WP1  = AL(O_Q    + (size_t)NNODES*100*4);
constexpr size_t O_WP1B = AL(O_WP1  + (size_t)512*1200*4);
constexpr size_t O_WPC  = AL(O_WP1B + (size_t)512*800*4);
constexpr size_t O_WP2  = AL(O_WPC  + (size_t)512*400*4);
constexpr size_t O_SUM  = AL(O_WP2  + (size_t)1200*600*4);
constexpr size_t O_SSQ  = AL(O_SUM  + (size_t)1200*4);
constexpr size_t O_S    = AL(O_SSQ  + (size_t)1200*4);
constexpr size_t O_T    = AL(O_S    + (size_t)1200*4);
constexpr size_t O_XH  = AL(O_T   + (size_t)1200*4);
constexpr size_t O_XL  = AL(O_XH  + (size_t)NNODES*512*2);
constexpr size_t O_T1H = AL(O_XL  + (size_t)NNODES*512*2);
constexpr size_t O_T1L = AL(O_T1H + (size_t)NNODES*512*2);
constexpr size_t O_T2H = AL(O_T1L + (size_t)NNODES*512*2);
constexpr size_t O_T2L = AL(O_T2H + (size_t)NNODES*512*2);
constexpr size_t O_H1H = AL(O_T2L + (size_t)NNODES*512*2);
constexpr size_t O_H1L = AL(O_H1H + (size_t)NNODES*1200*2);
constexpr size_t O_W1H = AL(O_H1L + (size_t)NNODES*1200*2);
constexpr size_t O_W1L = AL(O_W1H + (size_t)512*1200*2);
constexpr size_t O_W1BH= AL(O_W1L + (size_t)512*1200*2);
constexpr size_t O_W1BL= AL(O_W1BH+ (size_t)512*800*2);
constexpr size_t O_W1CH= AL(O_W1BL+ (size_t)512*800*2);
constexpr size_t O_W1CL= AL(O_W1CH+ (size_t)512*400*2);
constexpr size_t O_W2H = AL(O_W1CL+ (size_t)512*400*2);
constexpr size_t O_W2L = AL(O_W2H + (size_t)1200*600*2);
constexpr size_t SCRATCH_BYTES = AL(O_W2L + (size_t)1200*600*2);

__device__ __align__(256) unsigned char g_scratch[SCRATCH_BYTES];

// ------------------------- graph prep -------------------------
__global__ void deg_kernel(const int* __restrict__ row, const float* __restrict__ w,
                           float* __restrict__ deg, int E) {
    for (int e = blockIdx.x * blockDim.x + threadIdx.x; e < E; e += gridDim.x * blockDim.x)
        atomicAdd(&deg[row[e]], w[e]);
}

__global__ void dis_kernel(const float* __restrict__ deg, float* __restrict__ dis, int n) {
    int i = blockIdx.x * blockDim.x + threadIdx.x;
    if (i < n) { float d = deg[i]; dis[i] = (d > 0.f) ? rsqrtf(d) : 0.f; }
}

__global__ void norm_cnt_kernel(const int* __restrict__ row, const int* __restrict__ col,
                                const float* __restrict__ w, const float* __restrict__ dis,
                                float* __restrict__ nrm, int* __restrict__ cnt, int E) {
    for (int e = blockIdx.x * blockDim.x + threadIdx.x; e < E; e += gridDim.x * blockDim.x) {
        int r = row[e], c = col[e];
        nrm[e] = -dis[r] * w[e] * dis[c];
        atomicAdd(&cnt[c], 1);
    }
}

__global__ void scan_kernel(const int* __restrict__ cnt, int n, int* __restrict__ colptr) {
    __shared__ int part[1024];
    int tid = threadIdx.x;
    int per = (n + 1023) / 1024;
    int s0 = tid * per, s1 = min(s0 + per, n);
    int s = 0;
    for (int i = s0; i < s1; i++) s += cnt[i];
    part[tid] = s;
    __syncthreads();
    for (int off = 1; off < 1024; off <<= 1) {
        int v = (tid >= off) ? part[tid - off] : 0;
        __syncthreads();
        part[tid] += v;
        __syncthreads();
    }
    int prefix = (tid == 0) ? 0 : part[tid - 1];
    for (int i = s0; i < s1; i++) { colptr[i] = prefix; prefix += cnt[i]; }
    if (tid == 0) colptr[n] = part[1023];
}

__global__ void scatter_kernel(const int* __restrict__ row, const int* __restrict__ col,
                               const float* __restrict__ nrm, int* __restrict__ cursor,
                               int* __restrict__ erow, float* __restrict__ enorm, int E) {
    for (int e = blockIdx.x * blockDim.x + threadIdx.x; e < E; e += gridDim.x * blockDim.x) {
        int c = col[e];
        int p = atomicAdd(&cursor[c], 1);
        erow[p] = row[e];
        enorm[p] = nrm[e];
    }
}

// ---------------- transposed weight packing + bf16 split ----------------
// dst[(nOff + c) * ldk + r] = src[r * srcCols + c]   (W [K,C] -> Wt [N,K])
__global__ void pack_colsT(float* __restrict__ dst, int ldk, int nOff,
                           const float* __restrict__ src, int srcCols, int rowsK) {
    int total = rowsK * srcCols;
    for (int i = blockIdx.x * blockDim.x + threadIdx.x; i < total; i += gridDim.x * blockDim.x) {
        int r = i / srcCols, c = i - r * srcCols;
        dst[(size_t)(nOff + c) * ldk + r] = src[i];
    }
}

__global__ void split_kernel(const float2* __restrict__ src, bf162* __restrict__ hi,
                             bf162* __restrict__ lo, size_t n2) {
    for (size_t i = blockIdx.x * (size_t)blockDim.x + threadIdx.x; i < n2;
         i += (size_t)gridDim.x * blockDim.x) {
        float2 v = src[i];
        bf16 ax = __float2bfloat16(v.x), ay = __float2bfloat16(v.y);
        bf162 h; h.x = ax; h.y = ay;
        bf162 l;
        l.x = __float2bfloat16(v.x - __bfloat162float(ax));
        l.y = __float2bfloat16(v.y - __bfloat162float(ay));
        hi[i] = h; lo[i] = l;
    }
}

// ---------------- legacy-tensor split-GEMM (mma.sync, pipelined) ----------------
// C[M,N] (+)= Ah*Bt_h^T + Ah*Bt_l^T + Al*Bt_h^T, fp32 accum.
// A: [M,K] bf16 row-major. Bt: [N,K] bf16 row-major. K%16==0.

__device__ __forceinline__ void cp16(unsigned dst, const void* src, bool v) {
    int sz = v ? 16 : 0;
    asm volatile("cp.async.cg.shared.global [%0], [%1], 16, %2;"
                 :: "r"(dst), "l"(src), "r"(sz));
}

#define TSTR 24                       // tile row stride in bf16 (48B)
#define TILE_B (128 * TSTR * 2)       // 6144 bytes per tile
#define STAGE_B (4 * TILE_B)          // Ah, Al, Bh, Bl

__global__ __launch_bounds__(256, 2)
void bgemm_kernel(int M, int N, int K,
                  const bf16* __restrict__ Ah, const bf16* __restrict__ Al, int lda,
                  const bf16* __restrict__ Bh, const bf16* __restrict__ Bl, int ldb,
                  float* __restrict__ C, int ldc, int accum) {
    __shared__ __align__(16) unsigned char sm[2 * STAGE_B];
    const unsigned smb = (unsigned)__cvta_generic_to_shared(sm);

    const int tid = threadIdx.x, lane = tid & 31, wid = tid >> 5;
    const int warpM = wid & 1, warpN = wid >> 1;
    const int bm = blockIdx.y * 128, bn = blockIdx.x * 128;

    // loader mapping: each thread owns one 16B chunk per tile
    const int lRow = tid >> 1, lK8 = (tid & 1) * 8;
    const unsigned lOff = (unsigned)(lRow * TSTR + lK8) * 2u;
    const bool av = (bm + lRow) < M;
    const bool bv = (bn + lRow) < N;
    const size_t aRowOff = (size_t)min(bm + lRow, M - 1) * lda + lK8;
    const size_t bRowOff = (size_t)min(bn + lRow, N - 1) * ldb + lK8;

    // ldmatrix lane offsets (bytes within tile)
    const unsigned aLd = (unsigned)(((warpM * 64 + (lane & 15)) * TSTR + (lane >> 4) * 8) * 2);
    const unsigned bLd = (unsigned)(((warpN * 32 + (lane & 7)) * TSTR + ((lane >> 3) & 1) * 8) * 2);

    float acc[4][4][4];
#pragma unroll
    for (int mt = 0; mt < 4; mt++)
#pragma unroll
        for (int nt = 0; nt < 4; nt++)
#pragma unroll
            for (int i = 0; i < 4; i++) acc[mt][nt][i] = 0.f;

    const int nk = K / 16;

    auto prefetch = [&](int stage, int ch) {
        unsigned sb = smb + stage * STAGE_B;
        size_t ko = (size_t)(ch * 16);
        cp16(sb + 0 * TILE_B + lOff, Ah + aRowOff + ko, av);
        cp16(sb + 1 * TILE_B + lOff, Al + aRowOff + ko, av);
        cp16(sb + 2 * TILE_B + lOff, Bh + bRowOff + ko, bv);
        cp16(sb + 3 * TILE_B + lOff, Bl + bRowOff + ko, bv);
    };

    prefetch(0, 0);
    asm volatile("cp.async.commit_group;" ::: "memory");

    for (int it = 0; it < nk; ++it) {
        if (it + 1 < nk) prefetch((it + 1) & 1, it + 1);
        asm volatile("cp.async.commit_group;" ::: "memory");
        asm volatile("cp.async.wait_group 1;" ::: "memory");
        __syncthreads();

        unsigned sb = smb + (it & 1) * STAGE_B;
        unsigned a4[4][4], bh2[4][2], bl2[4][2];
#pragma unroll
        for (int mt = 0; mt < 4; mt++) {
            unsigned addr = sb + 0 * TILE_B + aLd + (unsigned)(mt * 16 * TSTR * 2);
            asm volatile("ldmatrix.sync.aligned.m8n8.x4.shared.b16 {%0,%1,%2,%3}, [%4];"
                         : "=r"(a4[mt][0]), "=r"(a4[mt][1]), "=r"(a4[mt][2]), "=r"(a4[mt][3])
                         : "r"(addr));
        }
#pragma unroll
        for (int nt = 0; nt < 4; nt++) {
            unsigned addr = sb + 2 * TILE_B + bLd + (unsigned)(nt * 8 * TSTR * 2);
            asm volatile("ldmatrix.sync.aligned.m8n8.x2.shared.b16 {%0,%1}, [%2];"
                         : "=r"(bh2[nt][0]), "=r"(bh2[nt][1]) : "r"(addr));
        }
#pragma unroll
        for (int nt = 0; nt < 4; nt++) {
            unsigned addr = sb + 3 * TILE_B + bLd + (unsigned)(nt * 8 * TSTR * 2);
            asm volatile("ldmatrix.sync.aligned.m8n8.x2.shared.b16 {%0,%1}, [%2];"
                         : "=r"(bl2[nt][0]), "=r"(bl2[nt][1]) : "r"(addr));
        }
#define MMA(ar, br)                                                              \
        asm volatile("mma.sync.aligned.m16n8k16.row.col.f32.bf16.bf16.f32 "      \
            "{%0,%1,%2,%3}, {%4,%5,%6,%7}, {%8,%9}, {%0,%1,%2,%3};"              \
            : "+f"(acc[mt][nt][0]), "+f"(acc[mt][nt][1]),                        \
              "+f"(acc[mt][nt][2]), "+f"(acc[mt][nt][3])                         \
            : "r"((ar)[0]), "r"((ar)[1]), "r"((ar)[2]), "r"((ar)[3]),            \
              "r"((br)[0]), "r"((br)[1]))
#pragma unroll
        for (int mt = 0; mt < 4; mt++)
#pragma unroll
            for (int nt = 0; nt < 4; nt++) { MMA(a4[mt], bh2[nt]); }
#pragma unroll
        for (int mt = 0; mt < 4; mt++)
#pragma unroll
            for (int nt = 0; nt < 4; nt++) { MMA(a4[mt], bl2[nt]); }
        // overwrite A-hi frags with A-lo
#pragma unroll
        for (int mt = 0; mt < 4; mt++) {
            unsigned addr = sb + 1 * TILE_B + aLd + (unsigned)(mt * 16 * TSTR * 2);
            asm volatile("ldmatrix.sync.aligned.m8n8.x4.shared.b16 {%0,%1,%2,%3}, [%4];"
                         : "=r"(a4[mt][0]), "=r"(a4[mt][1]), "=r"(a4[mt][2]), "=r"(a4[mt][3])
                         : "r"(addr));
        }
#pragma unroll
        for (int mt = 0; mt < 4; mt++)
#pragma unroll
            for (int nt = 0; nt < 4; nt++) { MMA(a4[mt], bh2[nt]); }
#undef MMA
        __syncthreads();
    }

    const int g = lane >> 2, t4 = lane & 3;
#pragma unroll
    for (int mt = 0; mt < 4; mt++) {
        int r0 = bm + warpM * 64 + mt * 16 + g;
#pragma unroll
        for (int nt = 0; nt < 4; nt++) {
            int c0 = bn + warpN * 32 + nt * 8 + t4 * 2;
            if (c0 >= N) continue;
            if (r0 < M) {
                float2* p = (float2*)(C + (size_t)r0 * ldc + c0);
                float2 v = make_float2(acc[mt][nt][0], acc[mt][nt][1]);
                if (accum) { float2 o = *p; v.x += o.x; v.y += o.y; }
                *p = v;
            }
            int r1 = r0 + 8;
            if (r1 < M) {
                float2* p = (float2*)(C + (size_t)r1 * ldc + c0);
                float2 v = make_float2(acc[mt][nt][2], acc[mt][nt][3]);
                if (accum) { float2 o = *p; v.x += o.x; v.y += o.y; }
                *p = v;
            }
        }
    }
}

static void run_bgemm(int M, int N, int K, const bf16* Ah, const bf16* Al, int lda,
                      const bf16* Bh, const bf16* Bl, int ldb,
                      float* C, int ldc, int accum) {
    dim3 grid((N + 127) / 128, (M + 127) / 128);
    bgemm_kernel<<<grid, 256>>>(M, N, K, Ah, Al, lda, Bh, Bl, ldb, C, ldc, accum);
}

// ------------------------- CSR prop -------------------------
__global__ void prop_kernel(const float4* __restrict__ src, int srcLd4,
                            float4* __restrict__ dst, int dstLd4, int D4,
                            float alpha, const float4* __restrict__ other, int otherLd4,
                            float beta, int accum,
                            const int* __restrict__ colptr, const int* __restrict__ erow,
                            const float* __restrict__ enorm) {
    int c = blockIdx.x, tid = threadIdx.x;
    __shared__ int sR[256];
    __shared__ float sW[256];
    int e0 = colptr[c], e1 = colptr[c + 1];
    float4 acc = make_float4(0, 0, 0, 0);
    for (int base = e0; base < e1; base += 256) {
        int cnt = min(256, e1 - base);
        for (int i = tid; i < cnt; i += blockDim.x) {
            sR[i] = erow[base + i];
            sW[i] = enorm[base + i];
        }
        __syncthreads();
        if (tid < D4) {
#pragma unroll 4
            for (int i = 0; i < cnt; i++) {
                float w = sW[i];
                float4 v = src[(size_t)sR[i] * srcLd4 + tid];
                acc.x += w * v.x; acc.y += w * v.y;
                acc.z += w * v.z; acc.w += w * v.w;
            }
        }
        __syncthreads();
    }
    if (tid < D4) {
        float4 r = make_float4(alpha * acc.x, alpha * acc.y, alpha * acc.z, alpha * acc.w);
        if (other) {
            float4 ov = other[(size_t)c * otherLd4 + tid];
            r.x += beta * ov.x; r.y += beta * ov.y; r.z += beta * ov.z; r.w += beta * ov.w;
        }
        size_t o = (size_t)c * dstLd4 + tid;
        if (accum) {
            float4 d = dst[o];
            r.x += d.x; r.y += d.y; r.z += d.z; r.w += d.w;
        }
        dst[o] = r;
    }
}

// ------------------------- batchnorm -------------------------
__global__ void bn_stats(const float* __restrict__ H, int ld, int C, int rows,
                         int rpb, float* __restrict__ gsum, float* __restrict__ gsq) {
    int c = blockIdx.x * blockDim.x + threadIdx.x;
    if (c >= C) return;
    int r0 = blockIdx.y * rpb, r1 = min(r0 + rpb, rows);
    float s = 0.f, q = 0.f;
    for (int r = r0; r < r1; r++) {
        float v = H[(size_t)r * ld + c];
        s += v; q += v * v;
    }
    atomicAdd(&gsum[c], s);
    atomicAdd(&gsq[c], q);
}

__global__ void bn_finalize(const float* __restrict__ gsum, const float* __restrict__ gsq,
                            const float* __restrict__ g, const float* __restrict__ beta,
                            float* __restrict__ s, float* __restrict__ t, int C, float invN) {
    int c = blockIdx.x * blockDim.x + threadIdx.x;
    if (c >= C) return;
    float mu = gsum[c] * invN;
    float var = gsq[c] * invN - mu * mu;
    float rs = rsqrtf(var + 1e-5f) * g[c];
    s[c] = rs;
    t[c] = beta[c] - mu * rs;
}

__global__ void bn_apply_relu_split(const float2* __restrict__ H, const float* __restrict__ s,
                                    const float* __restrict__ t, bf162* __restrict__ hi,
                                    bf162* __restrict__ lo, size_t total2, int C2) {
    for (size_t i = blockIdx.x * (size_t)blockDim.x + threadIdx.x; i < total2;
         i += (size_t)gridDim.x * blockDim.x) {
        int c = (int)(i % C2) * 2;
        float2 v = H[i];
        float a = fmaxf(fmaf(v.x, s[c + 0], t[c + 0]), 0.f);
        float b = fmaxf(fmaf(v.y, s[c + 1], t[c + 1]), 0.f);
        bf16 ah = __float2bfloat16(a), bh = __float2bfloat16(b);
        bf162 h; h.x = ah; h.y = bh;
        bf162 l;
        l.x = __float2bfloat16(a - __bfloat162float(ah));
        l.y = __float2bfloat16(b - __bfloat162float(bh));
        hi[i] = h; lo[i] = l;
    }
}

// ---------------- final: BN2 + linear(300->10) + logsoftmax ----------------
__global__ void final_kernel(const float* __restrict__ Z, int ld,
                             const float* __restrict__ s, const float* __restrict__ t,
                             const float* __restrict__ Wl, const float* __restrict__ bl,
                             float* __restrict__ out, int rows) {
    __shared__ float sW[3000], ss[300], st[300], sb[16];
    int tid = threadIdx.x;
    for (int i = tid; i < 3000; i += 256) sW[i] = Wl[i];
    for (int i = tid; i < 300; i += 256) { ss[i] = s[i]; st[i] = t[i]; }
    if (tid < 10) sb[tid] = bl[tid];
    __syncthreads();
    int warp = tid >> 5, lane = tid & 31;
    int row = blockIdx.x * 8 + warp;
    if (row >= rows) return;
    float acc[10];
#pragma unroll
    for (int j = 0; j < 10; j++) acc[j] = 0.f;
    const float* zr = Z + (size_t)row * ld;
    for (int k = lane; k < 300; k += 32) {
        float h = fmaf(zr[k], ss[k], st[k]);
#pragma unroll
        for (int j = 0; j < 10; j++) acc[j] += h * sW[k * 10 + j];
    }
#pragma unroll
    for (int j = 0; j < 10; j++) {
#pragma unroll
        for (int o = 16; o > 0; o >>= 1) acc[j] += __shfl_xor_sync(0xffffffffu, acc[j], o);
        acc[j] += sb[j];
    }
    float m = acc[0];
#pragma unroll
    for (int j = 1; j < 10; j++) m = fmaxf(m, acc[j]);
    float sum = 0.f;
#pragma unroll
    for (int j = 0; j < 10; j++) sum += expf(acc[j] - m);
    float lse = m + logf(sum);
    if (lane < 10) out[(size_t)row * 10 + lane] = acc[lane] - lse;
}

// ------------------------- launch -------------------------
extern "C" void kernel_launch(void* const* d_in, const int* in_sizes, int n_in,
                              void* d_out, int out_size) {
    const float* x   = (const float*)d_in[0];
    const int*   eix = (const int*)  d_in[1];
    const float* ew  = (const float*)d_in[2];
    const float* W1a = (const float*)d_in[3];
    const float* W1b = (const float*)d_in[5];
    const float* W1c = (const float*)d_in[7];
    const float* g1  = (const float*)d_in[9];
    const float* be1 = (const float*)d_in[10];
    const float* W2a = (const float*)d_in[11];
    const float* W2b = (const float*)d_in[13];
    const float* W2c = (const float*)d_in[15];
    const float* g2  = (const float*)d_in[17];
    const float* be2 = (const float*)d_in[18];
    const float* Wl  = (const float*)d_in[19];
    const float* bl  = (const float*)d_in[20];
    float* out = (float*)d_out;

    unsigned char* base = nullptr;
    cudaGetSymbolAddress((void**)&base, g_scratch);

    float* deg  = (float*)(base + O_DEG);
    float* dis  = (float*)(base + O_DIS);
    float* nrm  = (float*)(base + O_NORM);
    int*   cnt  = (int*)  (base + O_CNT);
    int*   cptr = (int*)  (base + O_CPTR);
    int*   cur  = (int*)  (base + O_CUR);
    int*   erow = (int*)  (base + O_EROW);
    float* enrm = (float*)(base + O_ENRM);
    float* Tx1  = (float*)(base + O_TX1);
    float* Tx2  = (float*)(base + O_TX2);
    float* H1   = (float*)(base + O_H1);
    float* Z6   = (float*)(base + O_Z6);
    float* Q    = (float*)(base + O_Q);
    float* Wt1  = (float*)(base + O_WP1);
    float* Wt1b = (float*)(base + O_WP1B);
    float* Wt1c = (float*)(base + O_WPC);
    float* Wt2  = (float*)(base + O_WP2);
    float* gsum = (float*)(base + O_SUM);
    float* gsq  = (float*)(base + O_SSQ);
    float* bnS  = (float*)(base + O_S);
    float* bnT  = (float*)(base + O_T);
    bf16* xh  = (bf16*)(base + O_XH);   bf16* xl  = (bf16*)(base + O_XL);
    bf16* t1h = (bf16*)(base + O_T1H);  bf16* t1l = (bf16*)(base + O_T1L);
    bf16* t2h = (bf16*)(base + O_T2H);  bf16* t2l = (bf16*)(base + O_T2L);
    bf16* h1h = (bf16*)(base + O_H1H);  bf16* h1l = (bf16*)(base + O_H1L);
    bf16* w1h = (bf16*)(base + O_W1H);  bf16* w1l = (bf16*)(base + O_W1L);
    bf16* w1bh= (bf16*)(base + O_W1BH); bf16* w1bl= (bf16*)(base + O_W1BL);
    bf16* w1ch= (bf16*)(base + O_W1CH); bf16* w1cl= (bf16*)(base + O_W1CL);
    bf16* w2h = (bf16*)(base + O_W2H);  bf16* w2l = (bf16*)(base + O_W2L);

    const int* row = eix;
    const int* col = eix + NEDGE;

    // splits + transposed weight packing
    split_kernel<<<4096, 256>>>((const float2*)x, (bf162*)xh, (bf162*)xl,
                                (size_t)NNODES * 256);
    pack_colsT<<<256, 256>>>(Wt1, 512, 0,   W1a, 400, 512);
    pack_colsT<<<256, 256>>>(Wt1, 512, 400, W1b, 400, 512);
    pack_colsT<<<256, 256>>>(Wt1, 512, 800, W1c, 400, 512);
    split_kernel<<<1024, 256>>>((const float2*)Wt1, (bf162*)w1h, (bf162*)w1l, 307200);
    run_bgemm(NNODES, 1200, 512, xh, xl, 512, w1h, w1l, 512, H1, 1200, 0);

    // graph prep: degrees, norm, CSR-by-destination
    cudaMemsetAsync(deg, 0, (size_t)NNODES * 4);
    cudaMemsetAsync(cnt, 0, (size_t)NNODES * 4);
    deg_kernel<<<4096, 256>>>(row, ew, deg, NEDGE);
    dis_kernel<<<(NNODES + 255) / 256, 256>>>(deg, dis, NNODES);
    norm_cnt_kernel<<<4096, 256>>>(row, col, ew, dis, nrm, cnt, NEDGE);
    scan_kernel<<<1, 1024>>>(cnt, NNODES, cptr);
    cudaMemcpyAsync(cur, cptr, (size_t)NNODES * 4, cudaMemcpyDeviceToDevice);
    scatter_kernel<<<4096, 256>>>(row, col, nrm, cur, erow, enrm, NEDGE);

    // layer 1 remaining terms
    prop_kernel<<<NNODES, 128>>>((const float4*)x, 128, (float4*)Tx1, 128, 128,
                                 1.f, nullptr, 0, 0.f, 0, cptr, erow, enrm);
    split_kernel<<<4096, 256>>>((const float2*)Tx1, (bf162*)t1h, (bf162*)t1l,
                                (size_t)NNODES * 256);
    pack_colsT<<<256, 256>>>(Wt1b, 512, 0,   W1b + 204800, 400, 512);
    pack_colsT<<<256, 256>>>(Wt1b, 512, 400, W1c + 204800, 400, 512);
    split_kernel<<<1024, 256>>>((const float2*)Wt1b, (bf162*)w1bh, (bf162*)w1bl, 204800);
    run_bgemm(NNODES, 800, 512, t1h, t1l, 512, w1bh, w1bl, 512, H1 + 400, 1200, 1);

    prop_kernel<<<NNODES, 128>>>((const float4*)Tx1, 128, (float4*)Tx2, 128, 128,
                                 2.f, (const float4*)x, 128, -1.f, 0, cptr, erow, enrm);
    split_kernel<<<4096, 256>>>((const float2*)Tx2, (bf162*)t2h, (bf162*)t2l,
                                (size_t)NNODES * 256);
    pack_colsT<<<256, 256>>>(Wt1c, 512, 0, W1c + 409600, 400, 512);
    split_kernel<<<1024, 256>>>((const float2*)Wt1c, (bf162*)w1ch, (bf162*)w1cl, 102400);
    run_bgemm(NNODES, 400, 512, t2h, t2l, 512, w1ch, w1cl, 512, H1 + 800, 1200, 1);

    // BN1 + ReLU -> bf16 splits directly
    cudaMemsetAsync(gsum, 0, 1200 * 4);
    cudaMemsetAsync(gsq, 0, 1200 * 4);
    {
        dim3 g((1200 + 255) / 256, 20);
        bn_stats<<<g, 256>>>(H1, 1200, 1200, NNODES, 2500, gsum, gsq);
    }
    bn_finalize<<<(1200 + 255) / 256, 256>>>(gsum, gsq, g1, be1, bnS, bnT, 1200, 1.f / NNODES);
    bn_apply_relu_split<<<4096, 256>>>((const float2*)H1, bnS, bnT, (bf162*)h1h, (bf162*)h1l,
                                       (size_t)NNODES * 600, 600);

    // layer 2: GEMM-first (prop commutes with W)
    pack_colsT<<<256, 256>>>(Wt2, 1200, 0,   W2a,          100, 1200);
    pack_colsT<<<256, 256>>>(Wt2, 1200, 100, W2b,          100, 1200);
    pack_colsT<<<256, 256>>>(Wt2, 1200, 200, W2c,          100, 1200);
    pack_colsT<<<256, 256>>>(Wt2, 1200, 300, W2b + 120000, 100, 1200);
    pack_colsT<<<256, 256>>>(Wt2, 1200, 400, W2c + 120000, 100, 1200);
    pack_colsT<<<256, 256>>>(Wt2, 1200, 500, W2c + 240000, 100, 1200);
    split_kernel<<<1024, 256>>>((const float2*)Wt2, (bf162*)w2h, (bf162*)w2l, 360000);
    run_bgemm(NNODES, 600, 1200, h1h, h1l, 1200, w2h, w2l, 1200, Z6, 600, 0);

    // Z6[:,100:300] += prop(Z6[:,300:500])
    prop_kernel<<<NNODES, 64>>>((const float4*)(Z6 + 300), 150, (float4*)(Z6 + 100), 150, 50,
                                1.f, nullptr, 0, 0.f, 1, cptr, erow, enrm);
    // Q = prop(Z6[:,500:600])
    prop_kernel<<<NNODES, 32>>>((const float4*)(Z6 + 500), 150, (float4*)Q, 25, 25,
                                1.f, nullptr, 0, 0.f, 0, cptr, erow, enrm);
    // Z6[:,200:300] += 2*prop(Q) - Z6[:,500:600]
    prop_kernel<<<NNODES, 32>>>((const float4*)Q, 25, (float4*)(Z6 + 200), 150, 25,
                                2.f, (const float4*)(Z6 + 500), 150, -1.f, 1, cptr, erow, enrm);

    // BN2 stats
    cudaMemsetAsync(gsum, 0, 300 * 4);
    cudaMemsetAsync(gsq, 0, 300 * 4);
    {
        dim3 g((300 + 255) / 256, 20);
        bn_stats<<<g, 256>>>(Z6, 600, 300, NNODES, 2500, gsum, gsq);
    }
    bn_finalize<<<(300 + 255) / 256, 256>>>(gsum, gsq, g2, be2, bnS, bnT, 300, 1.f / NNODES);

    // fused BN2 + linear + log_softmax
    final_kernel<<<(NNODES + 7) / 8, 256>>>(Z6, 600, bnS, bnT, Wl, bl, out, NNODES);
}